// round 2
// baseline (speedup 1.0000x reference)
#include <cuda_runtime.h>
#include <cuda_bf16.h>

// Problem constants (shapes fixed by the dataset; guards handle ragged tails anyway)
#define HF 128
#define MAX_NODES 100000

// Scratch: per-node precomputed layer-1 partials.
// C[n][0:64]   = h[n] @ W1[:, :128].T   (A part, for src)
// C[n][64:128] = h[n] @ W1[:, 128:].T   (B part, for dst)
__device__ float g_C[(size_t)MAX_NODES * 128];

// ---------------------------------------------------------------------------
// Kernel 1: per-node precompute  C = h @ G.T  (G is 128x128 rearranged W1)
// Block = 256 threads, 64 nodes/block, 8 nodes per inner iteration.
// Gt (transposed G) staged in SMEM: Gt[k][j], conflict-free float4 reads.
// ---------------------------------------------------------------------------
__global__ __launch_bounds__(256) void precompute_kernel(
    const float* __restrict__ h, const float* __restrict__ W1, int n_nodes)
{
    extern __shared__ float sm[];
    float* Gt = sm;             // 128*128 floats : Gt[k*128 + j] = G[j][k]
    float* hs = sm + 128 * 128; // 8*128 floats

    const int tid = threadIdx.x;

    // Stage Gt: G[j][k] = (j<64) ? W1[j][k] : W1[j-64][128+k]
    for (int idx = tid; idx < 128 * 128; idx += 256) {
        int j = idx >> 7;
        int k = idx & 127;
        float v = (j < 64) ? W1[j * 256 + k] : W1[(j - 64) * 256 + 128 + k];
        Gt[k * 128 + j] = v;
    }
    __syncthreads();

    const int nb   = blockIdx.x * 64;
    const int nsub = tid >> 5;   // warp id = node within group of 8
    const int lane = tid & 31;   // 4 outputs per lane

    for (int it = 0; it < 8; ++it) {
        const int n0 = nb + it * 8;
        // Load 8 h-rows (8*128 floats) cooperatively, one float4/thread
        {
            int n = n0 + nsub;
            float4 v = make_float4(0.f, 0.f, 0.f, 0.f);
            if (n < n_nodes) v = ((const float4*)h)[n * 32 + lane];
            ((float4*)hs)[tid] = v;
        }
        __syncthreads();

        const int n = n0 + nsub;
        const float* hrow = hs + nsub * 128;
        float4 acc = make_float4(0.f, 0.f, 0.f, 0.f);
        #pragma unroll
        for (int k = 0; k < 128; ++k) {
            float  hv = hrow[k];                                  // LDS broadcast
            float4 g  = *(const float4*)(Gt + k * 128 + lane * 4);// LDS.128, conflict-free
            acc.x = fmaf(hv, g.x, acc.x);
            acc.y = fmaf(hv, g.y, acc.y);
            acc.z = fmaf(hv, g.z, acc.z);
            acc.w = fmaf(hv, g.w, acc.w);
        }
        if (n < n_nodes)
            ((float4*)g_C)[n * 32 + lane] = acc;
        __syncthreads();
    }
}

// ---------------------------------------------------------------------------
// Kernel 2: per-edge MLP.
//   X  = relu(C[src][0:64] + C[dst][64:128] + b1)   [64]
//   Y  = relu(X @ W2.T + b2)                        [32]
//   z  = Y @ W3.T + b3                              [6]
// 256 threads/block, 256 edges/block (1 edge/thread for compute),
// cooperative coalesced gather into SMEM first (16 lanes per 256B row).
// ---------------------------------------------------------------------------
#define XS_STRIDE 68   // 64 + 4 pad: odd multiple of 4 -> conflict-free row access

__global__ __launch_bounds__(256, 2) void edge_mlp_kernel(
    const int* __restrict__ src, const int* __restrict__ dst,
    const float* __restrict__ b1, const float* __restrict__ W2,
    const float* __restrict__ b2, const float* __restrict__ W3,
    const float* __restrict__ b3, float* __restrict__ out, int n_edges)
{
    extern __shared__ float sm[];
    float* Xs  = sm;                    // 256 * 68
    float* W2s = sm + 256 * XS_STRIDE;  // 2048
    float* W3s = W2s + 2048;            // 192
    float* b1s = W3s + 192;             // 64
    float* b2s = b1s + 64;              // 32
    float* b3s = b2s + 32;              // 8 (pad)
    int*   ss  = (int*)(b3s + 8);       // 256
    int*   ds  = ss + 256;              // 256

    const int tid = threadIdx.x;
    const int e0  = blockIdx.x * 256;

    // Stage weights/biases + edge indices
    for (int idx = tid; idx < 2048; idx += 256) W2s[idx] = W2[idx];
    if (tid < 192) W3s[tid] = W3[tid];
    if (tid < 64)  b1s[tid] = b1[tid];
    if (tid < 32)  b2s[tid] = b2[tid];
    if (tid < 6)   b3s[tid] = b3[tid];
    {
        int e = e0 + tid;
        ss[tid] = (e < n_edges) ? src[e] : 0;
        ds[tid] = (e < n_edges) ? dst[e] : 0;
    }
    __syncthreads();

    // Cooperative gather: A part (C[src][0:64]) — 16 lanes per edge-row,
    // each lane one float4 -> fully coalesced 256B row reads from L2.
    #pragma unroll
    for (int it = 0; it < 16; ++it) {
        int flat = it * 256 + tid;
        int e = flat >> 4;
        int q = flat & 15;
        int s = ss[e];
        float4 a = ((const float4*)g_C)[s * 32 + q];
        *(float4*)(Xs + e * XS_STRIDE + q * 4) = a;
    }
    __syncthreads();

    // B part (C[dst][64:128]) + b1 + relu, combined in place
    #pragma unroll
    for (int it = 0; it < 16; ++it) {
        int flat = it * 256 + tid;
        int e = flat >> 4;
        int q = flat & 15;
        int d = ds[e];
        float4 b  = ((const float4*)g_C)[d * 32 + 16 + q];
        float4 x  = *(float4*)(Xs + e * XS_STRIDE + q * 4);
        float4 bb = *(const float4*)(b1s + q * 4);
        x.x = fmaxf(x.x + b.x + bb.x, 0.f);
        x.y = fmaxf(x.y + b.y + bb.y, 0.f);
        x.z = fmaxf(x.z + b.z + bb.z, 0.f);
        x.w = fmaxf(x.w + b.w + bb.w, 0.f);
        *(float4*)(Xs + e * XS_STRIDE + q * 4) = x;
    }
    __syncthreads();

    // Per-thread edge compute
    const int eg = e0 + tid;

    float4 X4[16];
    #pragma unroll
    for (int q = 0; q < 16; ++q)
        X4[q] = *(const float4*)(Xs + tid * XS_STRIDE + q * 4); // conflict-free (stride 68)

    // Layer 2: [64] -> [32], W2 broadcast from SMEM (uniform address per warp)
    float Y[32];
    #pragma unroll
    for (int j = 0; j < 32; ++j) {
        float a0 = b2s[j], a1 = 0.f, a2 = 0.f, a3 = 0.f;
        #pragma unroll
        for (int q = 0; q < 16; ++q) {
            float4 w = *(const float4*)(W2s + j * 64 + q * 4);
            a0 = fmaf(X4[q].x, w.x, a0);
            a1 = fmaf(X4[q].y, w.y, a1);
            a2 = fmaf(X4[q].z, w.z, a2);
            a3 = fmaf(X4[q].w, w.w, a3);
        }
        Y[j] = fmaxf((a0 + a1) + (a2 + a3), 0.f);
    }

    // Layer 3: [32] -> [6]
    float z[6];
    #pragma unroll
    for (int o = 0; o < 6; ++o) {
        float a0 = b3s[o], a1 = 0.f, a2 = 0.f, a3 = 0.f;
        #pragma unroll
        for (int q = 0; q < 8; ++q) {
            float4 w = *(const float4*)(W3s + o * 32 + q * 4);
            a0 = fmaf(Y[4 * q + 0], w.x, a0);
            a1 = fmaf(Y[4 * q + 1], w.y, a1);
            a2 = fmaf(Y[4 * q + 2], w.z, a2);
            a3 = fmaf(Y[4 * q + 3], w.w, a3);
        }
        z[o] = (a0 + a1) + (a2 + a3);
    }

    if (eg < n_edges) {
        float2* op = (float2*)(out + (size_t)eg * 6); // eg*24B, 8B aligned
        op[0] = make_float2(z[0], z[1]);
        op[1] = make_float2(z[2], z[3]);
        op[2] = make_float2(z[4], z[5]);
    }
}

// ---------------------------------------------------------------------------
// Launch
// ---------------------------------------------------------------------------
extern "C" void kernel_launch(void* const* d_in, const int* in_sizes, int n_in,
                              void* d_out, int out_size)
{
    const float* h   = (const float*)d_in[0];
    const int*   src = (const int*)  d_in[1];
    const int*   dst = (const int*)  d_in[2];
    const float* W1  = (const float*)d_in[3];
    const float* b1  = (const float*)d_in[4];
    const float* W2  = (const float*)d_in[5];
    const float* b2  = (const float*)d_in[6];
    const float* W3  = (const float*)d_in[7];
    const float* b3  = (const float*)d_in[8];
    float* out = (float*)d_out;

    const int n_nodes = in_sizes[0] / HF;
    const int n_edges = in_sizes[1];

    const int smem1 = (128 * 128 + 8 * 128) * 4;                  // 69,632 B
    const int smem2 = (256 * XS_STRIDE + 2048 + 192 + 64 + 32 + 8) * 4
                      + 512 * 4;                                  // 81,056 B

    cudaFuncSetAttribute(precompute_kernel,
                         cudaFuncAttributeMaxDynamicSharedMemorySize, smem1);
    cudaFuncSetAttribute(edge_mlp_kernel,
                         cudaFuncAttributeMaxDynamicSharedMemorySize, smem2);

    precompute_kernel<<<(n_nodes + 63) / 64, 256, smem1>>>(h, W1, n_nodes);
    edge_mlp_kernel<<<(n_edges + 255) / 256, 256, smem2>>>(
        src, dst, b1, W2, b2, W3, b3, out, n_edges);
}

// round 3
// speedup vs baseline: 1.5240x; 1.5240x over previous
#include <cuda_runtime.h>
#include <cuda_bf16.h>

#define HF 128
#define MAX_NODES 100000

// Scratch: per-node precomputed layer-1 partials.
// C[n][0:64]   = h[n] @ W1[:, :128].T   (A part, for src)
// C[n][64:128] = h[n] @ W1[:, 128:].T   (B part, for dst)
__device__ float g_C[(size_t)MAX_NODES * 128];

// ---------------------------------------------------------------------------
// Kernel 1: per-node precompute  C = h @ G.T  (G is 128x128 rearranged W1)
// Register-blocked: 256 threads, 64 nodes x 128 outs per block.
// Thread (tx,ty): tx=lane owns out-quad [tx*4..tx*4+3], ty=warp owns 8 nodes.
// Per k: 1 lane-distinct Gt float4 (amortized over 8 nodes) + 8 warp-uniform
// h broadcasts -> FMA-pipe bound instead of crossbar bound.
// ---------------------------------------------------------------------------
__global__ __launch_bounds__(256, 2) void precompute_kernel(
    const float* __restrict__ h, const float* __restrict__ W1, int n_nodes)
{
    extern __shared__ float sm[];
    float* Gt = sm;             // [128][128] : Gt[k*128 + j] = G[j][k]
    float* hs = sm + 128 * 128; // [64][128]

    const int tid = threadIdx.x;
    const int nb  = blockIdx.x * 64;

    // Stage Gt: G[j][k] = (j<64) ? W1[j][k] : W1[j-64][128+k]
    for (int idx = tid; idx < 128 * 128; idx += 256) {
        int j = idx >> 7;
        int k = idx & 127;
        float v = (j < 64) ? W1[j * 256 + k] : W1[(j - 64) * 256 + 128 + k];
        Gt[k * 128 + j] = v;
    }
    // Stage 64 h rows (2048 float4, coalesced)
    for (int idx = tid; idx < 64 * 32; idx += 256) {
        int n = nb + (idx >> 5);
        int q = idx & 31;
        float4 v = make_float4(0.f, 0.f, 0.f, 0.f);
        if (n < n_nodes) v = ((const float4*)h)[(size_t)n * 32 + q];
        ((float4*)hs)[idx] = v;
    }
    __syncthreads();

    const int tx = tid & 31;   // out-quad
    const int ty = tid >> 5;   // node group (8 nodes)

    float4 acc[8];
    #pragma unroll
    for (int i = 0; i < 8; ++i) acc[i] = make_float4(0.f, 0.f, 0.f, 0.f);

    #pragma unroll 4
    for (int k = 0; k < 128; k += 4) {
        // 8 warp-uniform float4 broadcasts (h for this warp's 8 nodes, 4 k's)
        float4 hv[8];
        #pragma unroll
        for (int i = 0; i < 8; ++i)
            hv[i] = *(const float4*)(hs + (ty * 8 + i) * 128 + k);

        #pragma unroll
        for (int kk = 0; kk < 4; ++kk) {
            float4 g = *(const float4*)(Gt + (k + kk) * 128 + tx * 4);
            #pragma unroll
            for (int i = 0; i < 8; ++i) {
                float hvv = (kk == 0) ? hv[i].x : (kk == 1) ? hv[i].y
                          : (kk == 2) ? hv[i].z : hv[i].w;
                acc[i].x = fmaf(hvv, g.x, acc[i].x);
                acc[i].y = fmaf(hvv, g.y, acc[i].y);
                acc[i].z = fmaf(hvv, g.z, acc[i].z);
                acc[i].w = fmaf(hvv, g.w, acc[i].w);
            }
        }
    }

    #pragma unroll
    for (int i = 0; i < 8; ++i) {
        int n = nb + ty * 8 + i;
        if (n < n_nodes)
            ((float4*)g_C)[(size_t)n * 32 + tx] = acc[i];
    }
}

// ---------------------------------------------------------------------------
// Kernel 2: per-edge MLP, warp-autonomous.
//   X  = relu(C[src][0:64] + C[dst][64:128] + b1)   [64]
//   Y  = relu(X @ W2.T + b2)                        [32]
//   z  = Y @ W3.T + b3                              [6]
// Each warp owns 32 edges: cooperative gather into a private SMEM slice
// (indices broadcast via shfl), then 1 edge/lane compute. Only __syncwarp
// after the initial weight staging -> gather/compute overlap across warps.
// ---------------------------------------------------------------------------
#define XS_STRIDE 68   // 64 + 4 pad -> conflict-free per-lane row reads

__global__ __launch_bounds__(256, 2) void edge_mlp_kernel(
    const int* __restrict__ src, const int* __restrict__ dst,
    const float* __restrict__ b1, const float* __restrict__ W2,
    const float* __restrict__ b2, const float* __restrict__ W3,
    const float* __restrict__ b3, float* __restrict__ out, int n_edges)
{
    extern __shared__ float sm[];
    float* W2s = sm;            // 2048
    float* W3s = sm + 2048;     // 192
    float* b1s = W3s + 192;     // 64
    float* b2s = b1s + 64;      // 32
    float* b3s = b2s + 32;      // 8 (pad; total prefix = 2344 floats, 16B-mult)
    float* Xs  = b3s + 8;       // 8 warps * 32 * 68

    const int tid  = threadIdx.x;
    const int lane = tid & 31;
    const int w    = tid >> 5;

    // Stage weights/biases once
    for (int idx = tid; idx < 2048; idx += 256) W2s[idx] = W2[idx];
    if (tid < 192) W3s[tid] = W3[tid];
    if (tid < 64)  b1s[tid] = b1[tid];
    if (tid < 32)  b2s[tid] = b2[tid];
    if (tid < 6)   b3s[tid] = b3[tid];
    __syncthreads();

    const int eg = blockIdx.x * 256 + w * 32 + lane;
    const int s  = (eg < n_edges) ? src[eg] : 0;
    const int d  = (eg < n_edges) ? dst[eg] : 0;

    float* Xw = Xs + w * (32 * XS_STRIDE);
    const int q  = lane & 15;        // quad within a 256B row
    const int eh = lane >> 4;        // which of 2 edges this half-warp handles

    // Gather A part: C[src][0:64] -> Xw, 2 edge-rows per warp-load (coalesced 512B)
    #pragma unroll
    for (int it = 0; it < 16; ++it) {
        int el   = it * 2 + eh;
        int srow = __shfl_sync(0xffffffffu, s, el);
        float4 a = ((const float4*)g_C)[(size_t)srow * 32 + q];
        *(float4*)(Xw + el * XS_STRIDE + q * 4) = a;
    }
    __syncwarp();

    // B part + b1 + relu in place
    #pragma unroll
    for (int it = 0; it < 16; ++it) {
        int el   = it * 2 + eh;
        int drow = __shfl_sync(0xffffffffu, d, el);
        float4 b  = ((const float4*)g_C)[(size_t)drow * 32 + 16 + q];
        float4 x  = *(float4*)(Xw + el * XS_STRIDE + q * 4);
        float4 bb = *(const float4*)(b1s + q * 4);
        x.x = fmaxf(x.x + b.x + bb.x, 0.f);
        x.y = fmaxf(x.y + b.y + bb.y, 0.f);
        x.z = fmaxf(x.z + b.z + bb.z, 0.f);
        x.w = fmaxf(x.w + b.w + bb.w, 0.f);
        *(float4*)(Xw + el * XS_STRIDE + q * 4) = x;
    }
    __syncwarp();

    // Per-lane edge compute: lane owns edge `lane` of this warp's tile
    float4 X4[16];
    #pragma unroll
    for (int p = 0; p < 16; ++p)
        X4[p] = *(const float4*)(Xw + lane * XS_STRIDE + p * 4); // conflict-free

    // Layer 2: [64] -> [32], W2 rows are warp-uniform broadcasts
    float Y[32];
    #pragma unroll
    for (int j = 0; j < 32; ++j) {
        float a0 = b2s[j], a1 = 0.f, a2 = 0.f, a3 = 0.f;
        #pragma unroll
        for (int p = 0; p < 16; ++p) {
            float4 wv = *(const float4*)(W2s + j * 64 + p * 4);
            a0 = fmaf(X4[p].x, wv.x, a0);
            a1 = fmaf(X4[p].y, wv.y, a1);
            a2 = fmaf(X4[p].z, wv.z, a2);
            a3 = fmaf(X4[p].w, wv.w, a3);
        }
        Y[j] = fmaxf((a0 + a1) + (a2 + a3), 0.f);
    }

    // Layer 3: [32] -> [6]
    float z[6];
    #pragma unroll
    for (int o = 0; o < 6; ++o) {
        float a0 = b3s[o], a1 = 0.f, a2 = 0.f, a3 = 0.f;
        #pragma unroll
        for (int p = 0; p < 8; ++p) {
            float4 wv = *(const float4*)(W3s + o * 32 + p * 4);
            a0 = fmaf(Y[4 * p + 0], wv.x, a0);
            a1 = fmaf(Y[4 * p + 1], wv.y, a1);
            a2 = fmaf(Y[4 * p + 2], wv.z, a2);
            a3 = fmaf(Y[4 * p + 3], wv.w, a3);
        }
        z[o] = (a0 + a1) + (a2 + a3);
    }

    if (eg < n_edges) {
        float2* op = (float2*)(out + (size_t)eg * 6);
        op[0] = make_float2(z[0], z[1]);
        op[1] = make_float2(z[2], z[3]);
        op[2] = make_float2(z[4], z[5]);
    }
}

// ---------------------------------------------------------------------------
// Launch
// ---------------------------------------------------------------------------
extern "C" void kernel_launch(void* const* d_in, const int* in_sizes, int n_in,
                              void* d_out, int out_size)
{
    const float* h   = (const float*)d_in[0];
    const int*   src = (const int*)  d_in[1];
    const int*   dst = (const int*)  d_in[2];
    const float* W1  = (const float*)d_in[3];
    const float* b1  = (const float*)d_in[4];
    const float* W2  = (const float*)d_in[5];
    const float* b2  = (const float*)d_in[6];
    const float* W3  = (const float*)d_in[7];
    const float* b3  = (const float*)d_in[8];
    float* out = (float*)d_out;

    const int n_nodes = in_sizes[0] / HF;
    const int n_edges = in_sizes[1];

    const int smem1 = (128 * 128 + 64 * 128) * 4;                 // 98,304 B
    const int smem2 = (2344 + 8 * 32 * XS_STRIDE) * 4;            // 79,008 B

    cudaFuncSetAttribute(precompute_kernel,
                         cudaFuncAttributeMaxDynamicSharedMemorySize, smem1);
    cudaFuncSetAttribute(edge_mlp_kernel,
                         cudaFuncAttributeMaxDynamicSharedMemorySize, smem2);

    precompute_kernel<<<(n_nodes + 63) / 64, 256, smem1>>>(h, W1, n_nodes);
    edge_mlp_kernel<<<(n_edges + 255) / 256, 256, smem2>>>(
        src, dst, b1, W2, b2, W3, b3, out, n_edges);
}

// round 4
// speedup vs baseline: 2.3456x; 1.5391x over previous
#include <cuda_runtime.h>
#include <cuda_bf16.h>
#include <cstdint>

#define HF 128
#define MAX_NODES 100000

// Per-node precomputed layer-1 partials:
// C[n][0:64] = h[n] @ W1[:, :128].T ; C[n][64:128] = h[n] @ W1[:, 128:].T
__device__ float g_C[(size_t)MAX_NODES * 128];

__device__ __forceinline__ float tf32r(float x) {
    asm("cvt.rna.tf32.f32 %0, %1;" : "=f"(x) : "f"(x));
    return x;
}

__device__ __forceinline__ void mma_tf32(float& c0, float& c1, float& c2, float& c3,
                                         uint32_t a0, uint32_t a1, uint32_t a2, uint32_t a3,
                                         uint32_t b0, uint32_t b1) {
    asm volatile(
        "mma.sync.aligned.m16n8k8.row.col.f32.tf32.tf32.f32 "
        "{%0,%1,%2,%3}, {%4,%5,%6,%7}, {%8,%9}, {%0,%1,%2,%3};"
        : "+f"(c0), "+f"(c1), "+f"(c2), "+f"(c3)
        : "r"(a0), "r"(a1), "r"(a2), "r"(a3), "r"(b0), "r"(b1));
}

// ---------------------------------------------------------------------------
// Kernel 1: C = h @ G.T via tf32 mma.  G[j][k] rearranged from W1.
// Block: 256 threads (8 warps), 128 nodes/block. Each warp: 16 nodes x 128 outs.
// B (Gt) staged in SMEM pre-arranged in fragment order -> conflict-free LDS.
// ---------------------------------------------------------------------------
#define HS_STRIDE 132   // 132 mod 32 == 4 -> conflict-free A-frag scalar loads

__global__ __launch_bounds__(256, 1) void precompute_kernel(
    const float* __restrict__ h, const float* __restrict__ W1, int n_nodes)
{
    extern __shared__ float sm[];
    float* hs = sm;                   // [128][HS_STRIDE]
    float* Bf = sm + 128 * HS_STRIDE; // 16 n x 16 k x 2 r x 32 lanes = 16384

    const int tid  = threadIdx.x;
    const int lane = tid & 31;
    const int w    = tid >> 5;
    const int nb   = blockIdx.x * 128;

    // Stage B fragments: Bf[((n*16+k)*2+r)*32+lane] = tf32(G[j][kk])
    //   j = n*8 + (lane>>2), kk = k*8 + (lane&3) + r*4
    for (int idx = tid; idx < 16384; idx += 256) {
        int l = idx & 31;
        int r = (idx >> 5) & 1;
        int k = (idx >> 6) & 15;
        int n = idx >> 10;
        int j  = n * 8 + (l >> 2);
        int kk = k * 8 + (l & 3) + r * 4;
        float v = (j < 64) ? W1[j * 256 + kk] : W1[(j - 64) * 256 + 128 + kk];
        Bf[idx] = tf32r(v);
    }
    // Stage 128 h rows (tf32-rounded), coalesced
    for (int idx = tid; idx < 128 * 128; idx += 256) {
        int row = idx >> 7;
        int kk  = idx & 127;
        int n   = nb + row;
        float v = (n < n_nodes) ? h[(size_t)n * 128 + kk] : 0.f;
        hs[row * HS_STRIDE + kk] = tf32r(v);
    }
    __syncthreads();

    // Warp w: nodes [nb + w*16, +16), all 128 outs (16 n-tiles), K=128 (16 k-tiles)
    const uint32_t* hsu = (const uint32_t*)hs;
    const uint32_t* Bfu = (const uint32_t*)Bf;
    const int rA = w * 16 + (lane >> 2);
    const int cA = lane & 3;

    float acc[16][4];
    #pragma unroll
    for (int n = 0; n < 16; ++n)
        acc[n][0] = acc[n][1] = acc[n][2] = acc[n][3] = 0.f;

    #pragma unroll
    for (int k = 0; k < 16; ++k) {
        uint32_t a0 = hsu[rA * HS_STRIDE + k * 8 + cA];
        uint32_t a1 = hsu[(rA + 8) * HS_STRIDE + k * 8 + cA];
        uint32_t a2 = hsu[rA * HS_STRIDE + k * 8 + cA + 4];
        uint32_t a3 = hsu[(rA + 8) * HS_STRIDE + k * 8 + cA + 4];
        #pragma unroll
        for (int n = 0; n < 16; ++n) {
            uint32_t b0 = Bfu[((n * 16 + k) * 2 + 0) * 32 + lane];
            uint32_t b1 = Bfu[((n * 16 + k) * 2 + 1) * 32 + lane];
            mma_tf32(acc[n][0], acc[n][1], acc[n][2], acc[n][3],
                     a0, a1, a2, a3, b0, b1);
        }
    }

    // Store C tile. c0,c1 = row r0 cols (2c,2c+1); c2,c3 = row r0+8.
    const int r0 = nb + w * 16 + (lane >> 2);
    #pragma unroll
    for (int n = 0; n < 16; ++n) {
        int col = n * 8 + 2 * (lane & 3);
        if (r0 < n_nodes)
            *(float2*)&g_C[(size_t)r0 * 128 + col] = make_float2(acc[n][0], acc[n][1]);
        if (r0 + 8 < n_nodes)
            *(float2*)&g_C[(size_t)(r0 + 8) * 128 + col] = make_float2(acc[n][2], acc[n][3]);
    }
}

// ---------------------------------------------------------------------------
// Kernel 2: per-edge MLP, warp-autonomous 32-edge tiles.
//   X = relu(C[src][0:64] + C[dst][64:128] + b1)  (tf32-rounded into SMEM)
//   Y = relu(X @ W2.T + b2)   via tf32 mma  [32x64]@[64x32]
//   z = Y @ W3.T + b3         scalar fp32, shfl-reduced
// ---------------------------------------------------------------------------
#define XS_STRIDE 68   // 68 mod 32 == 4 -> conflict-free frag loads + f4 rows

__global__ __launch_bounds__(256, 2) void edge_mlp_kernel(
    const int* __restrict__ src, const int* __restrict__ dst,
    const float* __restrict__ b1, const float* __restrict__ W2,
    const float* __restrict__ b2, const float* __restrict__ W3,
    const float* __restrict__ b3, float* __restrict__ out, int n_edges)
{
    extern __shared__ float sm[];
    float* W2f = sm;            // 4 n x 8 k x 2 r x 32 lanes = 2048 (frag order)
    float* W3s = sm + 2048;     // 192
    float* b1s = W3s + 192;     // 64
    float* b2s = b1s + 64;      // 32
    float* b3s = b2s + 32;      // 8 (pad)
    float* Zs  = b3s + 8;       // 8 warps * 192
    float* Xs  = Zs + 8 * 192;  // 8 warps * 32 * XS_STRIDE

    const int tid  = threadIdx.x;
    const int lane = tid & 31;
    const int w    = tid >> 5;

    // Stage W2 in fragment order: W2f[((n*8+k)*2+r)*32+l] = tf32(W2[j][kk]),
    //   j = n*8 + (l>>2), kk = k*8 + (l&3) + r*4
    for (int idx = tid; idx < 2048; idx += 256) {
        int l = idx & 31;
        int r = (idx >> 5) & 1;
        int k = (idx >> 6) & 7;
        int n = idx >> 9;
        int j  = n * 8 + (l >> 2);
        int kk = k * 8 + (l & 3) + r * 4;
        W2f[idx] = tf32r(W2[j * 64 + kk]);
    }
    if (tid < 192) W3s[tid] = W3[tid];
    if (tid < 64)  b1s[tid] = b1[tid];
    if (tid < 32)  b2s[tid] = b2[tid];
    if (tid < 6)   b3s[tid] = b3[tid];
    __syncthreads();

    const int e0 = blockIdx.x * 256 + w * 32;   // this warp's 32 edges
    const int eg = e0 + lane;
    const int s  = (eg < n_edges) ? src[eg] : 0;
    const int d  = (eg < n_edges) ? dst[eg] : 0;

    float* Xw = Xs + w * (32 * XS_STRIDE);
    const int q  = lane & 15;
    const int eh = lane >> 4;

    // Gather A part: C[src][0:64], 2 edge-rows per warp-load
    #pragma unroll
    for (int it = 0; it < 16; ++it) {
        int el   = it * 2 + eh;
        int srow = __shfl_sync(0xffffffffu, s, el);
        float4 a = ((const float4*)g_C)[(size_t)srow * 32 + q];
        *(float4*)(Xw + el * XS_STRIDE + q * 4) = a;
    }
    __syncwarp();

    // B part + b1 + relu + tf32 round, in place
    #pragma unroll
    for (int it = 0; it < 16; ++it) {
        int el   = it * 2 + eh;
        int drow = __shfl_sync(0xffffffffu, d, el);
        float4 b  = ((const float4*)g_C)[(size_t)drow * 32 + 16 + q];
        float4 x  = *(float4*)(Xw + el * XS_STRIDE + q * 4);
        float4 bb = *(const float4*)(b1s + q * 4);
        x.x = tf32r(fmaxf(x.x + b.x + bb.x, 0.f));
        x.y = tf32r(fmaxf(x.y + b.y + bb.y, 0.f));
        x.z = tf32r(fmaxf(x.z + b.z + bb.z, 0.f));
        x.w = tf32r(fmaxf(x.w + b.w + bb.w, 0.f));
        *(float4*)(Xw + el * XS_STRIDE + q * 4) = x;
    }
    __syncwarp();

    // Layer 2 via mma: D[32 edges x 32 outs] = X[32x64] @ W2T[64x32]
    const uint32_t* Xu  = (const uint32_t*)Xw;
    const uint32_t* W2u = (const uint32_t*)W2f;
    const int g  = lane >> 2;   // row group
    const int cA = lane & 3;

    float acc[2][4][4];
    #pragma unroll
    for (int m = 0; m < 2; ++m)
        #pragma unroll
        for (int n = 0; n < 4; ++n)
            acc[m][n][0] = acc[m][n][1] = acc[m][n][2] = acc[m][n][3] = 0.f;

    #pragma unroll
    for (int k = 0; k < 8; ++k) {
        uint32_t bfr[4][2];
        #pragma unroll
        for (int n = 0; n < 4; ++n) {
            bfr[n][0] = W2u[((n * 8 + k) * 2 + 0) * 32 + lane];
            bfr[n][1] = W2u[((n * 8 + k) * 2 + 1) * 32 + lane];
        }
        #pragma unroll
        for (int m = 0; m < 2; ++m) {
            int rA = m * 16 + g;
            uint32_t a0 = Xu[rA * XS_STRIDE + k * 8 + cA];
            uint32_t a1 = Xu[(rA + 8) * XS_STRIDE + k * 8 + cA];
            uint32_t a2 = Xu[rA * XS_STRIDE + k * 8 + cA + 4];
            uint32_t a3 = Xu[(rA + 8) * XS_STRIDE + k * 8 + cA + 4];
            #pragma unroll
            for (int n = 0; n < 4; ++n)
                mma_tf32(acc[m][n][0], acc[m][n][1], acc[m][n][2], acc[m][n][3],
                         a0, a1, a2, a3, bfr[n][0], bfr[n][1]);
        }
    }

    // Epilogue: Y = relu(acc + b2), then layer 3 (fp32) with shfl reduction.
    // Thread owns rows {m*16+g, m*16+g+8}, cols {n*8+2*cA, +1}.
    float Yv[2][4][2][2];  // [m][n][rsel][colsel]
    #pragma unroll
    for (int m = 0; m < 2; ++m)
        #pragma unroll
        for (int n = 0; n < 4; ++n) {
            int col = n * 8 + 2 * cA;
            float bb0 = b2s[col], bb1 = b2s[col + 1];
            Yv[m][n][0][0] = fmaxf(acc[m][n][0] + bb0, 0.f);
            Yv[m][n][0][1] = fmaxf(acc[m][n][1] + bb1, 0.f);
            Yv[m][n][1][0] = fmaxf(acc[m][n][2] + bb0, 0.f);
            Yv[m][n][1][1] = fmaxf(acc[m][n][3] + bb1, 0.f);
        }

    float z[2][2][6];  // [m][rsel][o], partial over this lane's 8 cols
    #pragma unroll
    for (int o = 0; o < 6; ++o) {
        float zp[2][2] = {{0.f, 0.f}, {0.f, 0.f}};
        #pragma unroll
        for (int n = 0; n < 4; ++n) {
            int col = n * 8 + 2 * cA;
            float w0 = W3s[o * 32 + col];
            float w1 = W3s[o * 32 + col + 1];
            #pragma unroll
            for (int m = 0; m < 2; ++m) {
                zp[m][0] = fmaf(Yv[m][n][0][0], w0, fmaf(Yv[m][n][0][1], w1, zp[m][0]));
                zp[m][1] = fmaf(Yv[m][n][1][0], w0, fmaf(Yv[m][n][1][1], w1, zp[m][1]));
            }
        }
        float bo = (cA == 0) ? b3s[o] : 0.f;
        #pragma unroll
        for (int m = 0; m < 2; ++m) {
            z[m][0][o] = zp[m][0] + bo;
            z[m][1][o] = zp[m][1] + bo;
        }
    }

    // Reduce across the 4 lanes (cA = 0..3) of each row group
    #pragma unroll
    for (int m = 0; m < 2; ++m)
        #pragma unroll
        for (int r = 0; r < 2; ++r)
            #pragma unroll
            for (int o = 0; o < 6; ++o) {
                float v = z[m][r][o];
                v += __shfl_xor_sync(0xffffffffu, v, 1);
                v += __shfl_xor_sync(0xffffffffu, v, 2);
                z[m][r][o] = v;
            }

    // cA==0 lanes stage 4 rows x 6 to Zs, then coalesced store
    float* Zw = Zs + w * 192;
    if (cA == 0) {
        #pragma unroll
        for (int m = 0; m < 2; ++m)
            #pragma unroll
            for (int r = 0; r < 2; ++r) {
                int e_loc = m * 16 + g + r * 8;
                #pragma unroll
                for (int o = 0; o < 6; ++o)
                    Zw[e_loc * 6 + o] = z[m][r][o];
            }
    }
    __syncwarp();

    #pragma unroll
    for (int it = 0; it < 6; ++it) {
        int idx   = it * 32 + lane;
        int e_loc = idx / 6;
        if (e0 + e_loc < n_edges)
            out[(size_t)e0 * 6 + idx] = Zw[idx];
    }
}

// ---------------------------------------------------------------------------
// Launch
// ---------------------------------------------------------------------------
extern "C" void kernel_launch(void* const* d_in, const int* in_sizes, int n_in,
                              void* d_out, int out_size)
{
    const float* h   = (const float*)d_in[0];
    const int*   src = (const int*)  d_in[1];
    const int*   dst = (const int*)  d_in[2];
    const float* W1  = (const float*)d_in[3];
    const float* b1  = (const float*)d_in[4];
    const float* W2  = (const float*)d_in[5];
    const float* b2  = (const float*)d_in[6];
    const float* W3  = (const float*)d_in[7];
    const float* b3  = (const float*)d_in[8];
    float* out = (float*)d_out;

    const int n_nodes = in_sizes[0] / HF;
    const int n_edges = in_sizes[1];

    const int smem1 = (128 * HS_STRIDE + 16384) * 4;                       // 133,120 B
    const int smem2 = (2048 + 192 + 64 + 32 + 8 + 8 * 192 + 8 * 32 * XS_STRIDE) * 4; // 85,152 B

    cudaFuncSetAttribute(precompute_kernel,
                         cudaFuncAttributeMaxDynamicSharedMemorySize, smem1);
    cudaFuncSetAttribute(edge_mlp_kernel,
                         cudaFuncAttributeMaxDynamicSharedMemorySize, smem2);

    precompute_kernel<<<(n_nodes + 127) / 128, 256, smem1>>>(h, W1, n_nodes);
    edge_mlp_kernel<<<(n_edges + 255) / 256, 256, smem2>>>(
        src, dst, b1, W2, b2, W3, b3, out, n_edges);
}

// round 5
// speedup vs baseline: 2.9006x; 1.2366x over previous
#include <cuda_runtime.h>
#include <cuda_bf16.h>
#include <cstdint>

#define HF 128
#define MAX_NODES 100000

// Per-node precomputed layer-1 partials:
// C[n][0:64] = h[n] @ W1[:, :128].T ; C[n][64:128] = h[n] @ W1[:, 128:].T
__device__ float g_C[(size_t)MAX_NODES * 128];

__device__ __forceinline__ float tf32r(float x) {
    asm("cvt.rna.tf32.f32 %0, %1;" : "=f"(x) : "f"(x));
    return x;
}

__device__ __forceinline__ void mma_tf32(float& c0, float& c1, float& c2, float& c3,
                                         uint32_t a0, uint32_t a1, uint32_t a2, uint32_t a3,
                                         uint32_t b0, uint32_t b1) {
    asm volatile(
        "mma.sync.aligned.m16n8k8.row.col.f32.tf32.tf32.f32 "
        "{%0,%1,%2,%3}, {%4,%5,%6,%7}, {%8,%9}, {%0,%1,%2,%3};"
        : "+f"(c0), "+f"(c1), "+f"(c2), "+f"(c3)
        : "r"(a0), "r"(a1), "r"(a2), "r"(a3), "r"(b0), "r"(b1));
}

// ---------------------------------------------------------------------------
// Kernel 1: C = h @ G.T via tf32 mma.  G[j][k] rearranged from W1.
// Block: 256 threads, 64 nodes (4 m-tiles). Warp w owns n-tiles {2w, 2w+1}.
// smem ~99 KB -> 2 blocks/SM (16 warps) for latency hiding.
// ---------------------------------------------------------------------------
#define HS_STRIDE 132   // 132 mod 32 == 4 -> conflict-free A-frag scalar loads

__global__ __launch_bounds__(256, 2) void precompute_kernel(
    const float* __restrict__ h, const float* __restrict__ W1, int n_nodes)
{
    extern __shared__ float sm[];
    float* hs = sm;                  // [64][HS_STRIDE] = 8448
    float* Bf = sm + 64 * HS_STRIDE; // 16 n x 16 k x 2 r x 32 lanes = 16384

    const int tid  = threadIdx.x;
    const int lane = tid & 31;
    const int w    = tid >> 5;
    const int nb   = blockIdx.x * 64;

    // Stage B fragments: Bf[((n*16+k)*2+r)*32+lane] = tf32(G[j][kk])
    //   j = n*8 + (lane>>2), kk = k*8 + (lane&3) + r*4
    for (int idx = tid; idx < 16384; idx += 256) {
        int l = idx & 31;
        int r = (idx >> 5) & 1;
        int k = (idx >> 6) & 15;
        int n = idx >> 10;
        int j  = n * 8 + (l >> 2);
        int kk = k * 8 + (l & 3) + r * 4;
        float v = (j < 64) ? W1[j * 256 + kk] : W1[(j - 64) * 256 + 128 + kk];
        Bf[idx] = tf32r(v);
    }
    // Stage 64 h rows (tf32-rounded), coalesced
    for (int idx = tid; idx < 64 * 128; idx += 256) {
        int row = idx >> 7;
        int kk  = idx & 127;
        int n   = nb + row;
        float v = (n < n_nodes) ? h[(size_t)n * 128 + kk] : 0.f;
        hs[row * HS_STRIDE + kk] = tf32r(v);
    }
    __syncthreads();

    const uint32_t* hsu = (const uint32_t*)hs;
    const uint32_t* Bfu = (const uint32_t*)Bf;
    const int g  = lane >> 2;
    const int cA = lane & 3;

    float acc[4][2][4];  // [m-tile][n-sub][frag]
    #pragma unroll
    for (int m = 0; m < 4; ++m)
        #pragma unroll
        for (int n = 0; n < 2; ++n)
            acc[m][n][0] = acc[m][n][1] = acc[m][n][2] = acc[m][n][3] = 0.f;

    #pragma unroll
    for (int k = 0; k < 16; ++k) {
        uint32_t a[4][4];
        #pragma unroll
        for (int m = 0; m < 4; ++m) {
            int rA = m * 16 + g;
            a[m][0] = hsu[rA * HS_STRIDE + k * 8 + cA];
            a[m][1] = hsu[(rA + 8) * HS_STRIDE + k * 8 + cA];
            a[m][2] = hsu[rA * HS_STRIDE + k * 8 + cA + 4];
            a[m][3] = hsu[(rA + 8) * HS_STRIDE + k * 8 + cA + 4];
        }
        #pragma unroll
        for (int n = 0; n < 2; ++n) {
            int nt = 2 * w + n;
            uint32_t b0 = Bfu[((nt * 16 + k) * 2 + 0) * 32 + lane];
            uint32_t b1 = Bfu[((nt * 16 + k) * 2 + 1) * 32 + lane];
            #pragma unroll
            for (int m = 0; m < 4; ++m)
                mma_tf32(acc[m][n][0], acc[m][n][1], acc[m][n][2], acc[m][n][3],
                         a[m][0], a[m][1], a[m][2], a[m][3], b0, b1);
        }
    }

    // Store. c0,c1 = row r0 cols (col, col+1); c2,c3 = row r0+8.
    #pragma unroll
    for (int m = 0; m < 4; ++m) {
        int r0 = nb + m * 16 + g;
        #pragma unroll
        for (int n = 0; n < 2; ++n) {
            int col = (2 * w + n) * 8 + 2 * cA;
            if (r0 < n_nodes)
                *(float2*)&g_C[(size_t)r0 * 128 + col] =
                    make_float2(acc[m][n][0], acc[m][n][1]);
            if (r0 + 8 < n_nodes)
                *(float2*)&g_C[(size_t)(r0 + 8) * 128 + col] =
                    make_float2(acc[m][n][2], acc[m][n][3]);
        }
    }
}

// ---------------------------------------------------------------------------
// Kernel 2: per-edge MLP, warp-autonomous 32-edge tiles, fused single-pass
// gather (A + B + b1 + relu + tf32 -> one STS), then tf32 mma layer 2,
// scalar fp32 layer 3 with shfl reduction.
// ---------------------------------------------------------------------------
#define XS_STRIDE 68   // 68 mod 32 == 4 -> conflict-free frag loads + f4 rows

__global__ __launch_bounds__(256, 2) void edge_mlp_kernel(
    const int* __restrict__ src, const int* __restrict__ dst,
    const float* __restrict__ b1, const float* __restrict__ W2,
    const float* __restrict__ b2, const float* __restrict__ W3,
    const float* __restrict__ b3, float* __restrict__ out, int n_edges)
{
    extern __shared__ float sm[];
    float* W2f = sm;            // 4 n x 8 k x 2 r x 32 lanes = 2048 (frag order)
    float* W3s = sm + 2048;     // 192
    float* b1s = W3s + 192;     // 64
    float* b2s = b1s + 64;      // 32
    float* b3s = b2s + 32;      // 8 (pad)
    float* Zs  = b3s + 8;       // 8 warps * 192
    float* Xs  = Zs + 8 * 192;  // 8 warps * 32 * XS_STRIDE

    const int tid  = threadIdx.x;
    const int lane = tid & 31;
    const int w    = tid >> 5;

    // Stage W2 in fragment order
    for (int idx = tid; idx < 2048; idx += 256) {
        int l = idx & 31;
        int r = (idx >> 5) & 1;
        int k = (idx >> 6) & 7;
        int n = idx >> 9;
        int j  = n * 8 + (l >> 2);
        int kk = k * 8 + (l & 3) + r * 4;
        W2f[idx] = tf32r(W2[j * 64 + kk]);
    }
    if (tid < 192) W3s[tid] = W3[tid];
    if (tid < 64)  b1s[tid] = b1[tid];
    if (tid < 32)  b2s[tid] = b2[tid];
    if (tid < 6)   b3s[tid] = b3[tid];
    __syncthreads();

    const int e0 = blockIdx.x * 256 + w * 32;   // this warp's 32 edges
    const int eg = e0 + lane;
    const int s  = (eg < n_edges) ? src[eg] : 0;
    const int d  = (eg < n_edges) ? dst[eg] : 0;

    float* Xw = Xs + w * (32 * XS_STRIDE);
    const int q  = lane & 15;
    const int eh = lane >> 4;
    const float4 bb = *(const float4*)(b1s + q * 4);  // loop-invariant

    // Fused gather: X[el] = tf32(relu(CA[src] + CB[dst] + b1)), single STS
    #pragma unroll
    for (int it = 0; it < 16; ++it) {
        int el   = it * 2 + eh;
        int srow = __shfl_sync(0xffffffffu, s, el);
        int drow = __shfl_sync(0xffffffffu, d, el);
        float4 a = ((const float4*)g_C)[(size_t)srow * 32 + q];
        float4 b = ((const float4*)g_C)[(size_t)drow * 32 + 16 + q];
        float4 x;
        x.x = tf32r(fmaxf(a.x + b.x + bb.x, 0.f));
        x.y = tf32r(fmaxf(a.y + b.y + bb.y, 0.f));
        x.z = tf32r(fmaxf(a.z + b.z + bb.z, 0.f));
        x.w = tf32r(fmaxf(a.w + b.w + bb.w, 0.f));
        *(float4*)(Xw + el * XS_STRIDE + q * 4) = x;
    }
    __syncwarp();

    // Layer 2 via mma: D[32 edges x 32 outs] = X[32x64] @ W2T[64x32]
    const uint32_t* Xu  = (const uint32_t*)Xw;
    const uint32_t* W2u = (const uint32_t*)W2f;
    const int g  = lane >> 2;
    const int cA = lane & 3;

    float acc[2][4][4];
    #pragma unroll
    for (int m = 0; m < 2; ++m)
        #pragma unroll
        for (int n = 0; n < 4; ++n)
            acc[m][n][0] = acc[m][n][1] = acc[m][n][2] = acc[m][n][3] = 0.f;

    #pragma unroll
    for (int k = 0; k < 8; ++k) {
        uint32_t bfr[4][2];
        #pragma unroll
        for (int n = 0; n < 4; ++n) {
            bfr[n][0] = W2u[((n * 8 + k) * 2 + 0) * 32 + lane];
            bfr[n][1] = W2u[((n * 8 + k) * 2 + 1) * 32 + lane];
        }
        #pragma unroll
        for (int m = 0; m < 2; ++m) {
            int rA = m * 16 + g;
            uint32_t a0 = Xu[rA * XS_STRIDE + k * 8 + cA];
            uint32_t a1 = Xu[(rA + 8) * XS_STRIDE + k * 8 + cA];
            uint32_t a2 = Xu[rA * XS_STRIDE + k * 8 + cA + 4];
            uint32_t a3 = Xu[(rA + 8) * XS_STRIDE + k * 8 + cA + 4];
            #pragma unroll
            for (int n = 0; n < 4; ++n)
                mma_tf32(acc[m][n][0], acc[m][n][1], acc[m][n][2], acc[m][n][3],
                         a0, a1, a2, a3, bfr[n][0], bfr[n][1]);
        }
    }

    // Epilogue: Y = relu(acc + b2), layer 3 fp32, shfl-reduce over cA lanes
    float Yv[2][4][2][2];
    #pragma unroll
    for (int m = 0; m < 2; ++m)
        #pragma unroll
        for (int n = 0; n < 4; ++n) {
            int col = n * 8 + 2 * cA;
            float bb0 = b2s[col], bb1 = b2s[col + 1];
            Yv[m][n][0][0] = fmaxf(acc[m][n][0] + bb0, 0.f);
            Yv[m][n][0][1] = fmaxf(acc[m][n][1] + bb1, 0.f);
            Yv[m][n][1][0] = fmaxf(acc[m][n][2] + bb0, 0.f);
            Yv[m][n][1][1] = fmaxf(acc[m][n][3] + bb1, 0.f);
        }

    float z[2][2][6];
    #pragma unroll
    for (int o = 0; o < 6; ++o) {
        float zp[2][2] = {{0.f, 0.f}, {0.f, 0.f}};
        #pragma unroll
        for (int n = 0; n < 4; ++n) {
            int col = n * 8 + 2 * cA;
            float w0 = W3s[o * 32 + col];
            float w1 = W3s[o * 32 + col + 1];
            #pragma unroll
            for (int m = 0; m < 2; ++m) {
                zp[m][0] = fmaf(Yv[m][n][0][0], w0, fmaf(Yv[m][n][0][1], w1, zp[m][0]));
                zp[m][1] = fmaf(Yv[m][n][1][0], w0, fmaf(Yv[m][n][1][1], w1, zp[m][1]));
            }
        }
        float bo = (cA == 0) ? b3s[o] : 0.f;
        #pragma unroll
        for (int m = 0; m < 2; ++m) {
            z[m][0][o] = zp[m][0] + bo;
            z[m][1][o] = zp[m][1] + bo;
        }
    }

    #pragma unroll
    for (int m = 0; m < 2; ++m)
        #pragma unroll
        for (int r = 0; r < 2; ++r)
            #pragma unroll
            for (int o = 0; o < 6; ++o) {
                float v = z[m][r][o];
                v += __shfl_xor_sync(0xffffffffu, v, 1);
                v += __shfl_xor_sync(0xffffffffu, v, 2);
                z[m][r][o] = v;
            }

    float* Zw = Zs + w * 192;
    if (cA == 0) {
        #pragma unroll
        for (int m = 0; m < 2; ++m)
            #pragma unroll
            for (int r = 0; r < 2; ++r) {
                int e_loc = m * 16 + g + r * 8;
                #pragma unroll
                for (int o = 0; o < 6; ++o)
                    Zw[e_loc * 6 + o] = z[m][r][o];
            }
    }
    __syncwarp();

    #pragma unroll
    for (int it = 0; it < 6; ++it) {
        int idx   = it * 32 + lane;
        int e_loc = idx / 6;
        if (e0 + e_loc < n_edges)
            out[(size_t)e0 * 6 + idx] = Zw[idx];
    }
}

// ---------------------------------------------------------------------------
// Launch
// ---------------------------------------------------------------------------
extern "C" void kernel_launch(void* const* d_in, const int* in_sizes, int n_in,
                              void* d_out, int out_size)
{
    const float* h   = (const float*)d_in[0];
    const int*   src = (const int*)  d_in[1];
    const int*   dst = (const int*)  d_in[2];
    const float* W1  = (const float*)d_in[3];
    const float* b1  = (const float*)d_in[4];
    const float* W2  = (const float*)d_in[5];
    const float* b2  = (const float*)d_in[6];
    const float* W3  = (const float*)d_in[7];
    const float* b3  = (const float*)d_in[8];
    float* out = (float*)d_out;

    const int n_nodes = in_sizes[0] / HF;
    const int n_edges = in_sizes[1];

    const int smem1 = (64 * HS_STRIDE + 16384) * 4;                        // 99,328 B
    const int smem2 = (2048 + 192 + 64 + 32 + 8 + 8 * 192 + 8 * 32 * XS_STRIDE) * 4; // 85,152 B

    cudaFuncSetAttribute(precompute_kernel,
                         cudaFuncAttributeMaxDynamicSharedMemorySize, smem1);
    cudaFuncSetAttribute(edge_mlp_kernel,
                         cudaFuncAttributeMaxDynamicSharedMemorySize, smem2);

    precompute_kernel<<<(n_nodes + 63) / 64, 256, smem1>>>(h, W1, n_nodes);
    edge_mlp_kernel<<<(n_edges + 255) / 256, 256, smem2>>>(
        src, dst, b1, W2, b2, W3, b3, out, n_edges);
}

// round 6
// speedup vs baseline: 4.2943x; 1.4805x over previous
#include <cuda_runtime.h>
#include <cuda_bf16.h>
#include <cstdint>

#define HF 128
#define MAX_NODES 100000

// Per-node precomputed layer-1 partials (b1 folded into A part):
// C[n][0:64] = h[n] @ W1[:, :128].T + b1 ; C[n][64:128] = h[n] @ W1[:, 128:].T
__device__ float g_C[(size_t)MAX_NODES * 128];
// One-shot fragment tables (tf32-rounded, mma B-fragment order)
__device__ float g_Bf[16384];   // layer-1 weights G (128x128 rearranged W1)
__device__ float g_W2f[2048];   // layer-2 weights

__device__ __forceinline__ float tf32r(float x) {
    asm("cvt.rna.tf32.f32 %0, %1;" : "=f"(x) : "f"(x));
    return x;
}

__device__ __forceinline__ void mma_tf32(float& c0, float& c1, float& c2, float& c3,
                                         uint32_t a0, uint32_t a1, uint32_t a2, uint32_t a3,
                                         uint32_t b0, uint32_t b1) {
    asm volatile(
        "mma.sync.aligned.m16n8k8.row.col.f32.tf32.tf32.f32 "
        "{%0,%1,%2,%3}, {%4,%5,%6,%7}, {%8,%9}, {%0,%1,%2,%3};"
        : "+f"(c0), "+f"(c1), "+f"(c2), "+f"(c3)
        : "r"(a0), "r"(a1), "r"(a2), "r"(a3), "r"(b0), "r"(b1));
}

// ---------------------------------------------------------------------------
// Kernel 0: build fragment tables once (64 blocks x 256).
//   g_Bf[((n*16+k)*2+r)*32+l] = tf32(G[j][kk]); j=n*8+(l>>2), kk=k*8+(l&3)+r*4
//   G[j][kk] = (j<64) ? W1[j][kk] : W1[j-64][128+kk]
//   g_W2f[((n*8+k)*2+r)*32+l] = tf32(W2[j][kk]); j=n*8+(l>>2), kk=k*8+(l&3)+r*4
// ---------------------------------------------------------------------------
__global__ void init_frag_kernel(const float* __restrict__ W1,
                                 const float* __restrict__ W2)
{
    int idx = blockIdx.x * 256 + threadIdx.x;
    if (idx < 16384) {
        int l = idx & 31;
        int r = (idx >> 5) & 1;
        int k = (idx >> 6) & 15;
        int n = idx >> 10;
        int j  = n * 8 + (l >> 2);
        int kk = k * 8 + (l & 3) + r * 4;
        float v = (j < 64) ? W1[j * 256 + kk] : W1[(j - 64) * 256 + 128 + kk];
        g_Bf[idx] = tf32r(v);
    }
    if (idx < 2048) {
        int l = idx & 31;
        int r = (idx >> 5) & 1;
        int k = (idx >> 6) & 7;
        int n = idx >> 9;
        int j  = n * 8 + (l >> 2);
        int kk = k * 8 + (l & 3) + r * 4;
        g_W2f[idx] = tf32r(W2[j * 64 + kk]);
    }
}

// ---------------------------------------------------------------------------
// Kernel 1: C = h @ G.T via tf32 mma, b1 folded into A-part columns.
// Block: 256 threads, 64 nodes (4 m-tiles). Warp w owns n-tiles {2w, 2w+1}.
// Bf copied from global table via float4; hs staged via float4.
// ---------------------------------------------------------------------------
#define HS_STRIDE 132   // mod 32 == 4 -> conflict-free A-frag scalar loads

__global__ __launch_bounds__(256, 2) void precompute_kernel(
    const float* __restrict__ h, const float* __restrict__ b1, int n_nodes)
{
    extern __shared__ float sm[];
    float* hs = sm;                  // [64][HS_STRIDE] = 8448
    float* Bf = sm + 64 * HS_STRIDE; // 16384

    const int tid  = threadIdx.x;
    const int lane = tid & 31;
    const int w    = tid >> 5;
    const int nb   = blockIdx.x * 64;

    // Copy Bf table (coalesced float4)
    {
        float4* dstp = (float4*)Bf;
        const float4* srcp = (const float4*)g_Bf;
        #pragma unroll
        for (int i = 0; i < 16; ++i)
            dstp[i * 256 + tid] = srcp[i * 256 + tid];
    }
    // Stage 64 h rows, tf32-rounded, via float4
    #pragma unroll
    for (int i = 0; i < 8; ++i) {
        int idx = i * 256 + tid;          // 0..2047 float4
        int row = idx >> 5;
        int q   = idx & 31;
        int n   = nb + row;
        float4 v = make_float4(0.f, 0.f, 0.f, 0.f);
        if (n < n_nodes) v = ((const float4*)h)[(size_t)n * 32 + q];
        v.x = tf32r(v.x); v.y = tf32r(v.y); v.z = tf32r(v.z); v.w = tf32r(v.w);
        *(float4*)(hs + row * HS_STRIDE + q * 4) = v;
    }
    __syncthreads();

    const uint32_t* hsu = (const uint32_t*)hs;
    const uint32_t* Bfu = (const uint32_t*)Bf;
    const int g  = lane >> 2;
    const int cA = lane & 3;

    // b1 fold values (A-part warps only: w<4 -> n-tiles 0..7 -> cols 0..63)
    float bv0[2] = {0.f, 0.f}, bv1[2] = {0.f, 0.f};
    if (w < 4) {
        #pragma unroll
        for (int n = 0; n < 2; ++n) {
            int col = (2 * w + n) * 8 + 2 * cA;
            bv0[n] = b1[col];
            bv1[n] = b1[col + 1];
        }
    }

    float acc[4][2][4];
    #pragma unroll
    for (int m = 0; m < 4; ++m)
        #pragma unroll
        for (int n = 0; n < 2; ++n)
            acc[m][n][0] = acc[m][n][1] = acc[m][n][2] = acc[m][n][3] = 0.f;

    #pragma unroll
    for (int k = 0; k < 16; ++k) {
        uint32_t a[4][4];
        #pragma unroll
        for (int m = 0; m < 4; ++m) {
            int rA = m * 16 + g;
            a[m][0] = hsu[rA * HS_STRIDE + k * 8 + cA];
            a[m][1] = hsu[(rA + 8) * HS_STRIDE + k * 8 + cA];
            a[m][2] = hsu[rA * HS_STRIDE + k * 8 + cA + 4];
            a[m][3] = hsu[(rA + 8) * HS_STRIDE + k * 8 + cA + 4];
        }
        #pragma unroll
        for (int n = 0; n < 2; ++n) {
            int nt = 2 * w + n;
            uint32_t b0 = Bfu[((nt * 16 + k) * 2 + 0) * 32 + lane];
            uint32_t b1f = Bfu[((nt * 16 + k) * 2 + 1) * 32 + lane];
            #pragma unroll
            for (int m = 0; m < 4; ++m)
                mma_tf32(acc[m][n][0], acc[m][n][1], acc[m][n][2], acc[m][n][3],
                         a[m][0], a[m][1], a[m][2], a[m][3], b0, b1f);
        }
    }

    // Store (+b1 on A part). c0,c1 = row r0; c2,c3 = row r0+8.
    #pragma unroll
    for (int m = 0; m < 4; ++m) {
        int r0 = nb + m * 16 + g;
        #pragma unroll
        for (int n = 0; n < 2; ++n) {
            int col = (2 * w + n) * 8 + 2 * cA;
            if (r0 < n_nodes)
                *(float2*)&g_C[(size_t)r0 * 128 + col] =
                    make_float2(acc[m][n][0] + bv0[n], acc[m][n][1] + bv1[n]);
            if (r0 + 8 < n_nodes)
                *(float2*)&g_C[(size_t)(r0 + 8) * 128 + col] =
                    make_float2(acc[m][n][2] + bv0[n], acc[m][n][3] + bv1[n]);
        }
    }
}

// ---------------------------------------------------------------------------
// Kernel 2: per-edge MLP, warp-autonomous 32-edge tiles, fused single-pass
// gather (A+B already includes b1; relu + tf32 -> one STS), tf32 mma layer 2,
// scalar fp32 layer 3 with shfl reduction.
// ---------------------------------------------------------------------------
#define XS_STRIDE 68   // mod 32 == 4 -> conflict-free frag loads + f4 rows

__global__ __launch_bounds__(256, 2) void edge_mlp_kernel(
    const int* __restrict__ src, const int* __restrict__ dst,
    const float* __restrict__ b2, const float* __restrict__ W3,
    const float* __restrict__ b3, float* __restrict__ out, int n_edges)
{
    extern __shared__ float sm[];
    float* W2f = sm;            // 2048 (frag order, copied from table)
    float* W3s = sm + 2048;     // 192
    float* b2s = W3s + 192;     // 32
    float* b3s = b2s + 32;      // 8 (pad; prefix = 2280 floats)
    float* Zs  = b3s + 8;       // 8 warps * 192 = 1536
    float* Xs  = Zs + 8 * 192;  // 8 warps * 32 * XS_STRIDE

    const int tid  = threadIdx.x;
    const int lane = tid & 31;
    const int w    = tid >> 5;

    // Copy W2f table (2 float4/thread), stage small constants
    {
        float4* dstp = (float4*)W2f;
        const float4* srcp = (const float4*)g_W2f;
        dstp[tid]       = srcp[tid];
        dstp[tid + 256] = srcp[tid + 256];
    }
    if (tid < 192) W3s[tid] = W3[tid];
    if (tid < 32)  b2s[tid] = b2[tid];
    if (tid < 6)   b3s[tid] = b3[tid];
    __syncthreads();

    const int e0 = blockIdx.x * 256 + w * 32;   // this warp's 32 edges
    const int eg = e0 + lane;
    const int s  = (eg < n_edges) ? src[eg] : 0;
    const int d  = (eg < n_edges) ? dst[eg] : 0;

    float* Xw = Xs + w * (32 * XS_STRIDE);
    const int q  = lane & 15;
    const int eh = lane >> 4;

    // Fused gather: X[el] = tf32(relu(CA'[src] + CB[dst])), single STS
    #pragma unroll
    for (int it = 0; it < 16; ++it) {
        int el   = it * 2 + eh;
        int srow = __shfl_sync(0xffffffffu, s, el);
        int drow = __shfl_sync(0xffffffffu, d, el);
        float4 a = ((const float4*)g_C)[(size_t)srow * 32 + q];
        float4 b = ((const float4*)g_C)[(size_t)drow * 32 + 16 + q];
        float4 x;
        x.x = tf32r(fmaxf(a.x + b.x, 0.f));
        x.y = tf32r(fmaxf(a.y + b.y, 0.f));
        x.z = tf32r(fmaxf(a.z + b.z, 0.f));
        x.w = tf32r(fmaxf(a.w + b.w, 0.f));
        *(float4*)(Xw + el * XS_STRIDE + q * 4) = x;
    }
    __syncwarp();

    // Layer 2 via mma: D[32 edges x 32 outs] = X[32x64] @ W2T[64x32]
    const uint32_t* Xu  = (const uint32_t*)Xw;
    const uint32_t* W2u = (const uint32_t*)W2f;
    const int g  = lane >> 2;
    const int cA = lane & 3;

    float acc[2][4][4];
    #pragma unroll
    for (int m = 0; m < 2; ++m)
        #pragma unroll
        for (int n = 0; n < 4; ++n)
            acc[m][n][0] = acc[m][n][1] = acc[m][n][2] = acc[m][n][3] = 0.f;

    #pragma unroll
    for (int k = 0; k < 8; ++k) {
        uint32_t bfr[4][2];
        #pragma unroll
        for (int n = 0; n < 4; ++n) {
            bfr[n][0] = W2u[((n * 8 + k) * 2 + 0) * 32 + lane];
            bfr[n][1] = W2u[((n * 8 + k) * 2 + 1) * 32 + lane];
        }
        #pragma unroll
        for (int m = 0; m < 2; ++m) {
            int rA = m * 16 + g;
            uint32_t a0 = Xu[rA * XS_STRIDE + k * 8 + cA];
            uint32_t a1 = Xu[(rA + 8) * XS_STRIDE + k * 8 + cA];
            uint32_t a2 = Xu[rA * XS_STRIDE + k * 8 + cA + 4];
            uint32_t a3 = Xu[(rA + 8) * XS_STRIDE + k * 8 + cA + 4];
            #pragma unroll
            for (int n = 0; n < 4; ++n)
                mma_tf32(acc[m][n][0], acc[m][n][1], acc[m][n][2], acc[m][n][3],
                         a0, a1, a2, a3, bfr[n][0], bfr[n][1]);
        }
    }

    // Epilogue: Y = relu(acc + b2), layer 3 fp32, shfl-reduce over cA lanes
    float Yv[2][4][2][2];
    #pragma unroll
    for (int m = 0; m < 2; ++m)
        #pragma unroll
        for (int n = 0; n < 4; ++n) {
            int col = n * 8 + 2 * cA;
            float bb0 = b2s[col], bb1 = b2s[col + 1];
            Yv[m][n][0][0] = fmaxf(acc[m][n][0] + bb0, 0.f);
            Yv[m][n][0][1] = fmaxf(acc[m][n][1] + bb1, 0.f);
            Yv[m][n][1][0] = fmaxf(acc[m][n][2] + bb0, 0.f);
            Yv[m][n][1][1] = fmaxf(acc[m][n][3] + bb1, 0.f);
        }

    float z[2][2][6];
    #pragma unroll
    for (int o = 0; o < 6; ++o) {
        float zp[2][2] = {{0.f, 0.f}, {0.f, 0.f}};
        #pragma unroll
        for (int n = 0; n < 4; ++n) {
            int col = n * 8 + 2 * cA;
            float w0 = W3s[o * 32 + col];
            float w1 = W3s[o * 32 + col + 1];
            #pragma unroll
            for (int m = 0; m < 2; ++m) {
                zp[m][0] = fmaf(Yv[m][n][0][0], w0, fmaf(Yv[m][n][0][1], w1, zp[m][0]));
                zp[m][1] = fmaf(Yv[m][n][1][0], w0, fmaf(Yv[m][n][1][1], w1, zp[m][1]));
            }
        }
        float bo = (cA == 0) ? b3s[o] : 0.f;
        #pragma unroll
        for (int m = 0; m < 2; ++m) {
            z[m][0][o] = zp[m][0] + bo;
            z[m][1][o] = zp[m][1] + bo;
        }
    }

    #pragma unroll
    for (int m = 0; m < 2; ++m)
        #pragma unroll
        for (int r = 0; r < 2; ++r)
            #pragma unroll
            for (int o = 0; o < 6; ++o) {
                float v = z[m][r][o];
                v += __shfl_xor_sync(0xffffffffu, v, 1);
                v += __shfl_xor_sync(0xffffffffu, v, 2);
                z[m][r][o] = v;
            }

    float* Zw = Zs + w * 192;
    if (cA == 0) {
        #pragma unroll
        for (int m = 0; m < 2; ++m)
            #pragma unroll
            for (int r = 0; r < 2; ++r) {
                int e_loc = m * 16 + g + r * 8;
                #pragma unroll
                for (int o = 0; o < 6; ++o)
                    Zw[e_loc * 6 + o] = z[m][r][o];
            }
    }
    __syncwarp();

    #pragma unroll
    for (int it = 0; it < 6; ++it) {
        int idx   = it * 32 + lane;
        int e_loc = idx / 6;
        if (e0 + e_loc < n_edges)
            out[(size_t)e0 * 6 + idx] = Zw[idx];
    }
}

// ---------------------------------------------------------------------------
// Launch
// ---------------------------------------------------------------------------
extern "C" void kernel_launch(void* const* d_in, const int* in_sizes, int n_in,
                              void* d_out, int out_size)
{
    const float* h   = (const float*)d_in[0];
    const int*   src = (const int*)  d_in[1];
    const int*   dst = (const int*)  d_in[2];
    const float* W1  = (const float*)d_in[3];
    const float* b1  = (const float*)d_in[4];
    const float* W2  = (const float*)d_in[5];
    const float* b2  = (const float*)d_in[6];
    const float* W3  = (const float*)d_in[7];
    const float* b3  = (const float*)d_in[8];
    float* out = (float*)d_out;

    const int n_nodes = in_sizes[0] / HF;
    const int n_edges = in_sizes[1];

    const int smem1 = (64 * HS_STRIDE + 16384) * 4;                        // 99,328 B
    const int smem2 = (2048 + 192 + 32 + 8 + 8 * 192 + 8 * 32 * XS_STRIDE) * 4; // 84,640 B

    cudaFuncSetAttribute(precompute_kernel,
                         cudaFuncAttributeMaxDynamicSharedMemorySize, smem1);
    cudaFuncSetAttribute(edge_mlp_kernel,
                         cudaFuncAttributeMaxDynamicSharedMemorySize, smem2);

    init_frag_kernel<<<64, 256>>>(W1, W2);
    precompute_kernel<<<(n_nodes + 63) / 64, 256, smem1>>>(h, b1, n_nodes);
    edge_mlp_kernel<<<(n_edges + 255) / 256, 256, smem2>>>(
        src, dst, b2, W3, b3, out, n_edges);
}

// round 7
// speedup vs baseline: 5.5861x; 1.3008x over previous
#include <cuda_runtime.h>
#include <cuda_bf16.h>
#include <cuda_fp16.h>
#include <cstdint>

#define HF 128
#define MAX_NODES 100000

// Per-node precomputed layer-1 partials, fp16, b1 folded into A part:
// C[n][0:64] = h[n] @ W1[:, :128].T + b1 ; C[n][64:128] = h[n] @ W1[:, 128:].T
// Stored as half2-packed uints: 64 uints per node row (128 halves).
__device__ uint32_t g_C[(size_t)MAX_NODES * 64];
// One-shot fragment tables
__device__ float    g_Bf[16384];   // layer-1 weights (tf32, mma B-frag order)
__device__ uint32_t g_W2h[1024];   // layer-2 weights (fp16 half2, m16n8k16 B-frag order)

__device__ __forceinline__ float tf32r(float x) {
    asm("cvt.rna.tf32.f32 %0, %1;" : "=f"(x) : "f"(x));
    return x;
}

__device__ __forceinline__ void mma_tf32(float& c0, float& c1, float& c2, float& c3,
                                         uint32_t a0, uint32_t a1, uint32_t a2, uint32_t a3,
                                         uint32_t b0, uint32_t b1) {
    asm volatile(
        "mma.sync.aligned.m16n8k8.row.col.f32.tf32.tf32.f32 "
        "{%0,%1,%2,%3}, {%4,%5,%6,%7}, {%8,%9}, {%0,%1,%2,%3};"
        : "+f"(c0), "+f"(c1), "+f"(c2), "+f"(c3)
        : "r"(a0), "r"(a1), "r"(a2), "r"(a3), "r"(b0), "r"(b1));
}

__device__ __forceinline__ void mma_f16(float& c0, float& c1, float& c2, float& c3,
                                        uint32_t a0, uint32_t a1, uint32_t a2, uint32_t a3,
                                        uint32_t b0, uint32_t b1) {
    asm volatile(
        "mma.sync.aligned.m16n8k16.row.col.f32.f16.f16.f32 "
        "{%0,%1,%2,%3}, {%4,%5,%6,%7}, {%8,%9}, {%0,%1,%2,%3};"
        : "+f"(c0), "+f"(c1), "+f"(c2), "+f"(c3)
        : "r"(a0), "r"(a1), "r"(a2), "r"(a3), "r"(b0), "r"(b1));
}

__device__ __forceinline__ void ldsm_x4(uint32_t& r0, uint32_t& r1,
                                        uint32_t& r2, uint32_t& r3, uint32_t addr) {
    asm volatile("ldmatrix.sync.aligned.m8n8.x4.shared.b16 {%0,%1,%2,%3}, [%4];"
                 : "=r"(r0), "=r"(r1), "=r"(r2), "=r"(r3) : "r"(addr));
}

__device__ __forceinline__ uint32_t hadd_relu(uint32_t a, uint32_t b) {
    __half2 s = __hadd2(*(__half2*)&a, *(__half2*)&b);
    s = __hmax2(s, __half2half2(__float2half(0.f)));
    return *(uint32_t*)&s;
}

__device__ __forceinline__ uint32_t pack_h2(float x, float y) {
    __half2 v = __floats2half2_rn(x, y);
    return *(uint32_t*)&v;
}

// ---------------------------------------------------------------------------
// Kernel 0: build fragment tables once.
//   g_Bf (tf32, m16n8k8 B-frag order) for layer 1:
//     g_Bf[((n*16+k)*2+r)*32+l] = tf32(G[j][kk]); j=n*8+(l>>2), kk=k*8+(l&3)+r*4
//     G[j][kk] = (j<64) ? W1[j][kk] : W1[j-64][128+kk]
//   g_W2h (fp16 half2, m16n8k16 B-frag order) for layer 2:
//     g_W2h[((nt*4+kt)*2+r)*32+l] = half2(W2[j][kk], W2[j][kk+1]);
//     j = nt*8+(l>>2), kk = kt*16 + 2*(l&3) + r*8
// ---------------------------------------------------------------------------
__global__ void init_frag_kernel(const float* __restrict__ W1,
                                 const float* __restrict__ W2)
{
    int idx = blockIdx.x * 256 + threadIdx.x;
    if (idx < 16384) {
        int l = idx & 31;
        int r = (idx >> 5) & 1;
        int k = (idx >> 6) & 15;
        int n = idx >> 10;
        int j  = n * 8 + (l >> 2);
        int kk = k * 8 + (l & 3) + r * 4;
        float v = (j < 64) ? W1[j * 256 + kk] : W1[(j - 64) * 256 + 128 + kk];
        g_Bf[idx] = tf32r(v);
    }
    if (idx < 1024) {
        int l  = idx & 31;
        int r  = (idx >> 5) & 1;
        int kt = (idx >> 6) & 3;
        int nt = idx >> 8;
        int j  = nt * 8 + (l >> 2);
        int kk = kt * 16 + 2 * (l & 3) + r * 8;
        g_W2h[idx] = pack_h2(W2[j * 64 + kk], W2[j * 64 + kk + 1]);
    }
}

// ---------------------------------------------------------------------------
// Kernel 1: C = h @ G.T via tf32 mma, b1 folded into A-part, fp16 store.
// Block: 256 threads, 64 nodes (4 m-tiles). Warp w owns n-tiles {2w, 2w+1}.
// ---------------------------------------------------------------------------
#define HS_STRIDE 132   // mod 32 == 4 -> conflict-free A-frag scalar loads

__global__ __launch_bounds__(256, 2) void precompute_kernel(
    const float* __restrict__ h, const float* __restrict__ b1, int n_nodes)
{
    extern __shared__ float sm[];
    float* hs = sm;                  // [64][HS_STRIDE] = 8448
    float* Bf = sm + 64 * HS_STRIDE; // 16384

    const int tid  = threadIdx.x;
    const int lane = tid & 31;
    const int w    = tid >> 5;
    const int nb   = blockIdx.x * 64;

    // Copy Bf table (coalesced float4)
    {
        float4* dstp = (float4*)Bf;
        const float4* srcp = (const float4*)g_Bf;
        #pragma unroll
        for (int i = 0; i < 16; ++i)
            dstp[i * 256 + tid] = srcp[i * 256 + tid];
    }
    // Stage 64 h rows, tf32-rounded, via float4
    #pragma unroll
    for (int i = 0; i < 8; ++i) {
        int idx = i * 256 + tid;
        int row = idx >> 5;
        int q   = idx & 31;
        int n   = nb + row;
        float4 v = make_float4(0.f, 0.f, 0.f, 0.f);
        if (n < n_nodes) v = ((const float4*)h)[(size_t)n * 32 + q];
        v.x = tf32r(v.x); v.y = tf32r(v.y); v.z = tf32r(v.z); v.w = tf32r(v.w);
        *(float4*)(hs + row * HS_STRIDE + q * 4) = v;
    }
    __syncthreads();

    const uint32_t* hsu = (const uint32_t*)hs;
    const uint32_t* Bfu = (const uint32_t*)Bf;
    const int g  = lane >> 2;
    const int cA = lane & 3;

    // b1 fold values (A-part warps only: w<4 -> n-tiles 0..7 -> cols 0..63)
    float bv0[2] = {0.f, 0.f}, bv1[2] = {0.f, 0.f};
    if (w < 4) {
        #pragma unroll
        for (int n = 0; n < 2; ++n) {
            int col = (2 * w + n) * 8 + 2 * cA;
            bv0[n] = b1[col];
            bv1[n] = b1[col + 1];
        }
    }

    float acc[4][2][4];
    #pragma unroll
    for (int m = 0; m < 4; ++m)
        #pragma unroll
        for (int n = 0; n < 2; ++n)
            acc[m][n][0] = acc[m][n][1] = acc[m][n][2] = acc[m][n][3] = 0.f;

    #pragma unroll
    for (int k = 0; k < 16; ++k) {
        uint32_t a[4][4];
        #pragma unroll
        for (int m = 0; m < 4; ++m) {
            int rA = m * 16 + g;
            a[m][0] = hsu[rA * HS_STRIDE + k * 8 + cA];
            a[m][1] = hsu[(rA + 8) * HS_STRIDE + k * 8 + cA];
            a[m][2] = hsu[rA * HS_STRIDE + k * 8 + cA + 4];
            a[m][3] = hsu[(rA + 8) * HS_STRIDE + k * 8 + cA + 4];
        }
        #pragma unroll
        for (int n = 0; n < 2; ++n) {
            int nt = 2 * w + n;
            uint32_t b0  = Bfu[((nt * 16 + k) * 2 + 0) * 32 + lane];
            uint32_t b1f = Bfu[((nt * 16 + k) * 2 + 1) * 32 + lane];
            #pragma unroll
            for (int m = 0; m < 4; ++m)
                mma_tf32(acc[m][n][0], acc[m][n][1], acc[m][n][2], acc[m][n][3],
                         a[m][0], a[m][1], a[m][2], a[m][3], b0, b1f);
        }
    }

    // Store fp16 (+b1 on A part). Cols (col,col+1) pack to one half2 uint.
    #pragma unroll
    for (int m = 0; m < 4; ++m) {
        int r0 = nb + m * 16 + g;
        #pragma unroll
        for (int n = 0; n < 2; ++n) {
            int hcol = (2 * w + n) * 4 + cA;   // half2 column index
            if (r0 < n_nodes)
                g_C[(size_t)r0 * 64 + hcol] =
                    pack_h2(acc[m][n][0] + bv0[n], acc[m][n][1] + bv1[n]);
            if (r0 + 8 < n_nodes)
                g_C[(size_t)(r0 + 8) * 64 + hcol] =
                    pack_h2(acc[m][n][2] + bv0[n], acc[m][n][3] + bv1[n]);
        }
    }
}

// ---------------------------------------------------------------------------
// Kernel 2: per-edge MLP, warp-autonomous 32-edge tiles, fp16 path.
//   Gather CA[src] + CB[dst] in fp16 (b1 pre-folded), relu -> X fp16 in SMEM.
//   Layer 2: fp16 mma m16n8k16 (A via ldmatrix, W2 frags preloaded to regs).
//   Layer 3: scalar fp32 with shfl reduction.
// ---------------------------------------------------------------------------
#define XH_STRIDE 72   // halves per X row (64 data + 8 pad); 144 B, 16B-aligned

__global__ __launch_bounds__(256, 2) void edge_mlp_kernel(
    const int* __restrict__ src, const int* __restrict__ dst,
    const float* __restrict__ b2, const float* __restrict__ W3,
    const float* __restrict__ b3, float* __restrict__ out, int n_edges)
{
    extern __shared__ float sm[];
    uint32_t* W2h = (uint32_t*)sm;             // 1024
    float* W3s = sm + 1024;                    // 192
    float* b2s = W3s + 192;                    // 32
    float* b3s = b2s + 32;                     // 8 (pad; prefix = 1256 words)
    float* Zs  = b3s + 8;                      // 8 * 192 = 1536
    uint32_t* Xs = (uint32_t*)(Zs + 8 * 192);  // 8 warps * 32 * 36 uints

    const int tid  = threadIdx.x;
    const int lane = tid & 31;
    const int w    = tid >> 5;

    // Stage tables/constants (W2h: 1024 uints = 256 uint4)
    ((uint4*)W2h)[tid] = ((const uint4*)g_W2h)[tid];
    if (tid < 192) W3s[tid] = W3[tid];
    if (tid < 32)  b2s[tid] = b2[tid];
    if (tid < 6)   b3s[tid] = b3[tid];
    __syncthreads();

    const int e0 = blockIdx.x * 256 + w * 32;
    const int eg = e0 + lane;
    const int s  = (eg < n_edges) ? src[eg] : 0;
    const int d  = (eg < n_edges) ? dst[eg] : 0;

    uint32_t* Xw = Xs + w * (32 * 36);
    const int q  = lane & 7;        // 16B chunk within 128B row-half
    const int eh = lane >> 3;       // 4 rows per warp-instruction
    const uint4* Cu = (const uint4*)g_C;

    // Fused gather: X[el] = relu_h2(CA[src] + CB[dst]), one STS.128 per 4 rows
    #pragma unroll
    for (int it = 0; it < 8; ++it) {
        int el   = it * 4 + eh;
        int srow = __shfl_sync(0xffffffffu, s, el);
        int drow = __shfl_sync(0xffffffffu, d, el);
        uint4 a = Cu[(size_t)srow * 16 + q];
        uint4 b = Cu[(size_t)drow * 16 + 8 + q];
        uint4 x;
        x.x = hadd_relu(a.x, b.x);
        x.y = hadd_relu(a.y, b.y);
        x.z = hadd_relu(a.z, b.z);
        x.w = hadd_relu(a.w, b.w);
        *(uint4*)(Xw + el * 36 + q * 4) = x;
    }
    __syncwarp();

    // Preload W2 fragments into registers (frag table, conflict-free LDS.32)
    uint32_t bf[4][4][2];
    #pragma unroll
    for (int nt = 0; nt < 4; ++nt)
        #pragma unroll
        for (int kt = 0; kt < 4; ++kt) {
            bf[nt][kt][0] = W2h[((nt * 4 + kt) * 2 + 0) * 32 + lane];
            bf[nt][kt][1] = W2h[((nt * 4 + kt) * 2 + 1) * 32 + lane];
        }

    // Layer 2: D[32x32] = X[32x64] @ W2T[64x32] via fp16 mma m16n8k16
    uint32_t xw_addr = (uint32_t)__cvta_generic_to_shared(Xw);
    // ldmatrix address: blk = lane>>3: {rows0-7 c0, rows8-15 c0, rows0-7 c8, rows8-15 c8}
    const int lrow = (lane & 7) + ((lane >> 3) & 1) * 8;
    const int lcolh = (lane >> 4) * 8;                    // halves
    uint32_t abase0 = xw_addr + (lrow * 36 + (lcolh >> 1)) * 4;           // m=0
    uint32_t abase1 = abase0 + 16 * 36 * 4;                               // m=1

    float acc[2][4][4];
    #pragma unroll
    for (int m = 0; m < 2; ++m)
        #pragma unroll
        for (int n = 0; n < 4; ++n)
            acc[m][n][0] = acc[m][n][1] = acc[m][n][2] = acc[m][n][3] = 0.f;

    #pragma unroll
    for (int kt = 0; kt < 4; ++kt) {
        uint32_t A0[4], A1[4];
        ldsm_x4(A0[0], A0[1], A0[2], A0[3], abase0 + kt * 32);
        ldsm_x4(A1[0], A1[1], A1[2], A1[3], abase1 + kt * 32);
        #pragma unroll
        for (int n = 0; n < 4; ++n) {
            mma_f16(acc[0][n][0], acc[0][n][1], acc[0][n][2], acc[0][n][3],
                    A0[0], A0[1], A0[2], A0[3], bf[n][kt][0], bf[n][kt][1]);
            mma_f16(acc[1][n][0], acc[1][n][1], acc[1][n][2], acc[1][n][3],
                    A1[0], A1[1], A1[2], A1[3], bf[n][kt][0], bf[n][kt][1]);
        }
    }

    // Epilogue: Y = relu(acc + b2), layer 3 fp32, shfl-reduce over cA lanes
    const int g  = lane >> 2;
    const int cA = lane & 3;

    float Yv[2][4][2][2];
    #pragma unroll
    for (int m = 0; m < 2; ++m)
        #pragma unroll
        for (int n = 0; n < 4; ++n) {
            int col = n * 8 + 2 * cA;
            float bb0 = b2s[col], bb1 = b2s[col + 1];
            Yv[m][n][0][0] = fmaxf(acc[m][n][0] + bb0, 0.f);
            Yv[m][n][0][1] = fmaxf(acc[m][n][1] + bb1, 0.f);
            Yv[m][n][1][0] = fmaxf(acc[m][n][2] + bb0, 0.f);
            Yv[m][n][1][1] = fmaxf(acc[m][n][3] + bb1, 0.f);
        }

    float z[2][2][6];
    #pragma unroll
    for (int o = 0; o < 6; ++o) {
        float zp[2][2] = {{0.f, 0.f}, {0.f, 0.f}};
        #pragma unroll
        for (int n = 0; n < 4; ++n) {
            int col = n * 8 + 2 * cA;
            float w0 = W3s[o * 32 + col];
            float w1 = W3s[o * 32 + col + 1];
            #pragma unroll
            for (int m = 0; m < 2; ++m) {
                zp[m][0] = fmaf(Yv[m][n][0][0], w0, fmaf(Yv[m][n][0][1], w1, zp[m][0]));
                zp[m][1] = fmaf(Yv[m][n][1][0], w0, fmaf(Yv[m][n][1][1], w1, zp[m][1]));
            }
        }
        float bo = (cA == 0) ? b3s[o] : 0.f;
        #pragma unroll
        for (int m = 0; m < 2; ++m) {
            z[m][0][o] = zp[m][0] + bo;
            z[m][1][o] = zp[m][1] + bo;
        }
    }

    #pragma unroll
    for (int m = 0; m < 2; ++m)
        #pragma unroll
        for (int r = 0; r < 2; ++r)
            #pragma unroll
            for (int o = 0; o < 6; ++o) {
                float v = z[m][r][o];
                v += __shfl_xor_sync(0xffffffffu, v, 1);
                v += __shfl_xor_sync(0xffffffffu, v, 2);
                z[m][r][o] = v;
            }

    float* Zw = Zs + w * 192;
    if (cA == 0) {
        #pragma unroll
        for (int m = 0; m < 2; ++m)
            #pragma unroll
            for (int r = 0; r < 2; ++r) {
                int e_loc = m * 16 + g + r * 8;
                #pragma unroll
                for (int o = 0; o < 6; ++o)
                    Zw[e_loc * 6 + o] = z[m][r][o];
            }
    }
    __syncwarp();

    #pragma unroll
    for (int it = 0; it < 6; ++it) {
        int idx   = it * 32 + lane;
        int e_loc = idx / 6;
        if (e0 + e_loc < n_edges)
            out[(size_t)e0 * 6 + idx] = Zw[idx];
    }
}

// ---------------------------------------------------------------------------
// Launch
// ---------------------------------------------------------------------------
extern "C" void kernel_launch(void* const* d_in, const int* in_sizes, int n_in,
                              void* d_out, int out_size)
{
    const float* h   = (const float*)d_in[0];
    const int*   src = (const int*)  d_in[1];
    const int*   dst = (const int*)  d_in[2];
    const float* W1  = (const float*)d_in[3];
    const float* b1  = (const float*)d_in[4];
    const float* W2  = (const float*)d_in[5];
    const float* b2  = (const float*)d_in[6];
    const float* W3  = (const float*)d_in[7];
    const float* b3  = (const float*)d_in[8];
    float* out = (float*)d_out;

    const int n_nodes = in_sizes[0] / HF;
    const int n_edges = in_sizes[1];

    const int smem1 = (64 * HS_STRIDE + 16384) * 4;              // 99,328 B
    const int smem2 = (1256 + 1536 + 8 * 32 * 36) * 4;           // 48,032 B

    cudaFuncSetAttribute(precompute_kernel,
                         cudaFuncAttributeMaxDynamicSharedMemorySize, smem1);
    cudaFuncSetAttribute(edge_mlp_kernel,
                         cudaFuncAttributeMaxDynamicSharedMemorySize, smem2);

    init_frag_kernel<<<64, 256>>>(W1, W2);
    precompute_kernel<<<(n_nodes + 63) / 64, 256, smem1>>>(h, b1, n_nodes);
    edge_mlp_kernel<<<(n_edges + 255) / 256, 256, smem2>>>(
        src, dst, b2, W3, b3, out, n_edges);
}

// round 8
// speedup vs baseline: 6.3936x; 1.1446x over previous
#include <cuda_runtime.h>
#include <cuda_bf16.h>
#include <cuda_fp16.h>
#include <cstdint>

#define HF 128
#define MAX_NODES 100000

// Per-node precomputed layer-1 partials, fp16, b1 folded into A part:
// C[n][0:64] = h[n] @ W1[:, :128].T + b1 ; C[n][64:128] = h[n] @ W1[:, 128:].T
// Stored as half2-packed uints: 64 uints per node row (128 halves).
__device__ uint32_t g_C[(size_t)MAX_NODES * 64];
// One-shot fragment tables (fp16 half2, m16n8k16 B-frag order)
__device__ uint32_t g_Bh[8192];    // layer-1 weights G (128x128 rearranged W1)
__device__ uint32_t g_W2h[1024];   // layer-2 weights

__device__ __forceinline__ void mma_f16(float& c0, float& c1, float& c2, float& c3,
                                        uint32_t a0, uint32_t a1, uint32_t a2, uint32_t a3,
                                        uint32_t b0, uint32_t b1) {
    asm volatile(
        "mma.sync.aligned.m16n8k16.row.col.f32.f16.f16.f32 "
        "{%0,%1,%2,%3}, {%4,%5,%6,%7}, {%8,%9}, {%0,%1,%2,%3};"
        : "+f"(c0), "+f"(c1), "+f"(c2), "+f"(c3)
        : "r"(a0), "r"(a1), "r"(a2), "r"(a3), "r"(b0), "r"(b1));
}

__device__ __forceinline__ void ldsm_x4(uint32_t& r0, uint32_t& r1,
                                        uint32_t& r2, uint32_t& r3, uint32_t addr) {
    asm volatile("ldmatrix.sync.aligned.m8n8.x4.shared.b16 {%0,%1,%2,%3}, [%4];"
                 : "=r"(r0), "=r"(r1), "=r"(r2), "=r"(r3) : "r"(addr));
}

__device__ __forceinline__ uint32_t hadd_relu(uint32_t a, uint32_t b) {
    __half2 s = __hadd2(*(__half2*)&a, *(__half2*)&b);
    s = __hmax2(s, __half2half2(__float2half(0.f)));
    return *(uint32_t*)&s;
}

__device__ __forceinline__ uint32_t pack_h2(float x, float y) {
    __half2 v = __floats2half2_rn(x, y);
    return *(uint32_t*)&v;
}

// ---------------------------------------------------------------------------
// Kernel 0: build fragment tables once (fp16 m16n8k16 B-frag order).
//   g_Bh[((nt*8+kt)*2+r)*32+l] = half2(G[j][kk], G[j][kk+1])
//     j = nt*8+(l>>2), kk = kt*16 + 2*(l&3) + r*8
//     G[j][kk] = (j<64) ? W1[j][kk] : W1[j-64][128+kk]
//   g_W2h[((nt*4+kt)*2+r)*32+l] = half2(W2[j][kk], W2[j][kk+1]), same index law
// ---------------------------------------------------------------------------
__global__ void init_frag_kernel(const float* __restrict__ W1,
                                 const float* __restrict__ W2)
{
    int idx = blockIdx.x * 256 + threadIdx.x;
    if (idx < 8192) {
        int l  = idx & 31;
        int r  = (idx >> 5) & 1;
        int kt = (idx >> 6) & 7;
        int nt = idx >> 9;
        int j  = nt * 8 + (l >> 2);
        int kk = kt * 16 + 2 * (l & 3) + r * 8;
        float v0, v1;
        if (j < 64) { v0 = W1[j * 256 + kk];            v1 = W1[j * 256 + kk + 1]; }
        else        { v0 = W1[(j - 64) * 256 + 128 + kk]; v1 = W1[(j - 64) * 256 + 128 + kk + 1]; }
        g_Bh[idx] = pack_h2(v0, v1);
    }
    if (idx < 1024) {
        int l  = idx & 31;
        int r  = (idx >> 5) & 1;
        int kt = (idx >> 6) & 3;
        int nt = idx >> 8;
        int j  = nt * 8 + (l >> 2);
        int kk = kt * 16 + 2 * (l & 3) + r * 8;
        g_W2h[idx] = pack_h2(W2[j * 64 + kk], W2[j * 64 + kk + 1]);
    }
}

// ---------------------------------------------------------------------------
// Kernel 1: C = h @ G.T via fp16 mma m16n8k16, b1 folded, fp16 store.
// Block: 256 threads, 64 nodes (4 m-tiles). Warp w owns n-tiles {2w, 2w+1}.
// hs: fp16 rows [64][HS2 uints], stride 68 (mod 32 == 4 -> conflict-free).
// ---------------------------------------------------------------------------
#define HS2 68

__global__ __launch_bounds__(256, 3) void precompute_kernel(
    const float* __restrict__ h, const float* __restrict__ b1, int n_nodes)
{
    extern __shared__ uint32_t smu[];
    uint32_t* hs = smu;              // [64][HS2] = 4352 uints
    uint32_t* Bh = smu + 64 * HS2;   // 8192 uints

    const int tid  = threadIdx.x;
    const int lane = tid & 31;
    const int w    = tid >> 5;
    const int nb   = blockIdx.x * 64;

    // Copy Bh table (coalesced uint4: 2048 uint4, 8/thread)
    {
        uint4* dstp = (uint4*)Bh;
        const uint4* srcp = (const uint4*)g_Bh;
        #pragma unroll
        for (int i = 0; i < 8; ++i)
            dstp[i * 256 + tid] = srcp[i * 256 + tid];
    }
    // Stage 64 h rows as fp16 (float4 -> uint2)
    #pragma unroll
    for (int i = 0; i < 8; ++i) {
        int idx = i * 256 + tid;          // 0..2047
        int row = idx >> 5;
        int q   = idx & 31;
        int n   = nb + row;
        float4 v = make_float4(0.f, 0.f, 0.f, 0.f);
        if (n < n_nodes) v = ((const float4*)h)[(size_t)n * 32 + q];
        uint2 p = make_uint2(pack_h2(v.x, v.y), pack_h2(v.z, v.w));
        *(uint2*)(hs + row * HS2 + 2 * q) = p;
    }
    __syncthreads();

    const int g  = lane >> 2;
    const int cA = lane & 3;

    // b1 fold values (A-part warps only: w<4 -> n-tiles 0..7 -> cols 0..63)
    float bv0[2] = {0.f, 0.f}, bv1[2] = {0.f, 0.f};
    if (w < 4) {
        #pragma unroll
        for (int n = 0; n < 2; ++n) {
            int col = (2 * w + n) * 8 + 2 * cA;
            bv0[n] = b1[col];
            bv1[n] = b1[col + 1];
        }
    }

    float acc[4][2][4];
    #pragma unroll
    for (int m = 0; m < 4; ++m)
        #pragma unroll
        for (int n = 0; n < 2; ++n)
            acc[m][n][0] = acc[m][n][1] = acc[m][n][2] = acc[m][n][3] = 0.f;

    #pragma unroll
    for (int kt = 0; kt < 8; ++kt) {
        uint32_t a[4][4];
        #pragma unroll
        for (int m = 0; m < 4; ++m) {
            int rA = m * 16 + g;
            a[m][0] = hs[rA * HS2 + kt * 8 + cA];
            a[m][1] = hs[(rA + 8) * HS2 + kt * 8 + cA];
            a[m][2] = hs[rA * HS2 + kt * 8 + cA + 4];
            a[m][3] = hs[(rA + 8) * HS2 + kt * 8 + cA + 4];
        }
        #pragma unroll
        for (int n = 0; n < 2; ++n) {
            int nt = 2 * w + n;
            uint32_t b0 = Bh[((nt * 8 + kt) * 2 + 0) * 32 + lane];
            uint32_t b1f = Bh[((nt * 8 + kt) * 2 + 1) * 32 + lane];
            #pragma unroll
            for (int m = 0; m < 4; ++m)
                mma_f16(acc[m][n][0], acc[m][n][1], acc[m][n][2], acc[m][n][3],
                        a[m][0], a[m][1], a[m][2], a[m][3], b0, b1f);
        }
    }

    // Store fp16 (+b1 on A part). Cols (2cA, 2cA+1) pack to one half2 uint.
    #pragma unroll
    for (int m = 0; m < 4; ++m) {
        int r0 = nb + m * 16 + g;
        #pragma unroll
        for (int n = 0; n < 2; ++n) {
            int hcol = (2 * w + n) * 4 + cA;
            if (r0 < n_nodes)
                g_C[(size_t)r0 * 64 + hcol] =
                    pack_h2(acc[m][n][0] + bv0[n], acc[m][n][1] + bv1[n]);
            if (r0 + 8 < n_nodes)
                g_C[(size_t)(r0 + 8) * 64 + hcol] =
                    pack_h2(acc[m][n][2] + bv0[n], acc[m][n][3] + bv1[n]);
        }
    }
}

// ---------------------------------------------------------------------------
// Kernel 2: per-edge MLP, warp-autonomous 32-edge tiles, fp16 path.
// launch_bounds(256,3): reg-capped for 24 warps/SM (gather-latency hiding).
// ---------------------------------------------------------------------------
__global__ __launch_bounds__(256, 3) void edge_mlp_kernel(
    const int* __restrict__ src, const int* __restrict__ dst,
    const float* __restrict__ b2, const float* __restrict__ W3,
    const float* __restrict__ b3, float* __restrict__ out, int n_edges)
{
    extern __shared__ float sm[];
    uint32_t* W2h = (uint32_t*)sm;             // 1024
    float* W3s = sm + 1024;                    // 192
    float* b2s = W3s + 192;                    // 32
    float* b3s = b2s + 32;                     // 8 (pad; prefix = 1256 words)
    float* Zs  = b3s + 8;                      // 8 * 192 = 1536
    uint32_t* Xs = (uint32_t*)(Zs + 8 * 192);  // 8 warps * 32 * 36 uints

    const int tid  = threadIdx.x;
    const int lane = tid & 31;
    const int w    = tid >> 5;

    // Issue edge-index loads early (overlap with staging)
    const int e0 = blockIdx.x * 256 + w * 32;
    const int eg = e0 + lane;
    const int s  = (eg < n_edges) ? src[eg] : 0;
    const int d  = (eg < n_edges) ? dst[eg] : 0;

    // Stage tables/constants (W2h: 1024 uints = 256 uint4)
    ((uint4*)W2h)[tid] = ((const uint4*)g_W2h)[tid];
    if (tid < 192) W3s[tid] = W3[tid];
    if (tid < 32)  b2s[tid] = b2[tid];
    if (tid < 6)   b3s[tid] = b3[tid];
    __syncthreads();

    uint32_t* Xw = Xs + w * (32 * 36);
    const int q  = lane & 7;        // 16B chunk within 128B row-half
    const int eh = lane >> 3;       // 4 rows per warp-instruction
    const uint4* Cu = (const uint4*)g_C;

    // Fused gather: X[el] = relu_h2(CA[src] + CB[dst]), one STS.128 per 4 rows
    #pragma unroll
    for (int it = 0; it < 8; ++it) {
        int el   = it * 4 + eh;
        int srow = __shfl_sync(0xffffffffu, s, el);
        int drow = __shfl_sync(0xffffffffu, d, el);
        uint4 a = Cu[(size_t)srow * 16 + q];
        uint4 b = Cu[(size_t)drow * 16 + 8 + q];
        uint4 x;
        x.x = hadd_relu(a.x, b.x);
        x.y = hadd_relu(a.y, b.y);
        x.z = hadd_relu(a.z, b.z);
        x.w = hadd_relu(a.w, b.w);
        *(uint4*)(Xw + el * 36 + q * 4) = x;
    }
    __syncwarp();

    // Layer 2: D[32x32] = X[32x64] @ W2T[64x32] via fp16 mma m16n8k16
    uint32_t xw_addr = (uint32_t)__cvta_generic_to_shared(Xw);
    const int lrow  = (lane & 7) + ((lane >> 3) & 1) * 8;
    const int lcolh = (lane >> 4) * 8;
    uint32_t abase0 = xw_addr + (lrow * 36 + (lcolh >> 1)) * 4;   // m=0
    uint32_t abase1 = abase0 + 16 * 36 * 4;                       // m=1

    float acc[2][4][4];
    #pragma unroll
    for (int m = 0; m < 2; ++m)
        #pragma unroll
        for (int n = 0; n < 4; ++n)
            acc[m][n][0] = acc[m][n][1] = acc[m][n][2] = acc[m][n][3] = 0.f;

    #pragma unroll
    for (int kt = 0; kt < 4; ++kt) {
        uint32_t A0[4], A1[4];
        ldsm_x4(A0[0], A0[1], A0[2], A0[3], abase0 + kt * 32);
        ldsm_x4(A1[0], A1[1], A1[2], A1[3], abase1 + kt * 32);
        #pragma unroll
        for (int n = 0; n < 4; ++n) {
            uint32_t b0 = W2h[((n * 4 + kt) * 2 + 0) * 32 + lane];
            uint32_t b1f = W2h[((n * 4 + kt) * 2 + 1) * 32 + lane];
            mma_f16(acc[0][n][0], acc[0][n][1], acc[0][n][2], acc[0][n][3],
                    A0[0], A0[1], A0[2], A0[3], b0, b1f);
            mma_f16(acc[1][n][0], acc[1][n][1], acc[1][n][2], acc[1][n][3],
                    A1[0], A1[1], A1[2], A1[3], b0, b1f);
        }
    }

    // Epilogue: Y = relu(acc + b2); layer 3 fp32 streamed per-o to cap regs.
    const int g  = lane >> 2;
    const int cA = lane & 3;

    float Yv[2][4][2][2];
    #pragma unroll
    for (int m = 0; m < 2; ++m)
        #pragma unroll
        for (int n = 0; n < 4; ++n) {
            int col = n * 8 + 2 * cA;
            float bb0 = b2s[col], bb1 = b2s[col + 1];
            Yv[m][n][0][0] = fmaxf(acc[m][n][0] + bb0, 0.f);
            Yv[m][n][0][1] = fmaxf(acc[m][n][1] + bb1, 0.f);
            Yv[m][n][1][0] = fmaxf(acc[m][n][2] + bb0, 0.f);
            Yv[m][n][1][1] = fmaxf(acc[m][n][3] + bb1, 0.f);
        }

    float* Zw = Zs + w * 192;
    #pragma unroll
    for (int o = 0; o < 6; ++o) {
        float zp[2][2] = {{0.f, 0.f}, {0.f, 0.f}};
        #pragma unroll
        for (int n = 0; n < 4; ++n) {
            int col = n * 8 + 2 * cA;
            float w0 = W3s[o * 32 + col];
            float w1 = W3s[o * 32 + col + 1];
            #pragma unroll
            for (int m = 0; m < 2; ++m) {
                zp[m][0] = fmaf(Yv[m][n][0][0], w0, fmaf(Yv[m][n][0][1], w1, zp[m][0]));
                zp[m][1] = fmaf(Yv[m][n][1][0], w0, fmaf(Yv[m][n][1][1], w1, zp[m][1]));
            }
        }
        #pragma unroll
        for (int m = 0; m < 2; ++m)
            #pragma unroll
            for (int r = 0; r < 2; ++r) {
                float v = zp[m][r];
                v += __shfl_xor_sync(0xffffffffu, v, 1);
                v += __shfl_xor_sync(0xffffffffu, v, 2);
                if (cA == 0)
                    Zw[(m * 16 + g + r * 8) * 6 + o] = v + b3s[o];
            }
    }
    __syncwarp();

    #pragma unroll
    for (int it = 0; it < 6; ++it) {
        int idx   = it * 32 + lane;
        int e_loc = idx / 6;
        if (e0 + e_loc < n_edges)
            out[(size_t)e0 * 6 + idx] = Zw[idx];
    }
}

// ---------------------------------------------------------------------------
// Launch
// ---------------------------------------------------------------------------
extern "C" void kernel_launch(void* const* d_in, const int* in_sizes, int n_in,
                              void* d_out, int out_size)
{
    const float* h   = (const float*)d_in[0];
    const int*   src = (const int*)  d_in[1];
    const int*   dst = (const int*)  d_in[2];
    const float* W1  = (const float*)d_in[3];
    const float* b1  = (const float*)d_in[4];
    const float* W2  = (const float*)d_in[5];
    const float* b2  = (const float*)d_in[6];
    const float* W3  = (const float*)d_in[7];
    const float* b3  = (const float*)d_in[8];
    float* out = (float*)d_out;

    const int n_nodes = in_sizes[0] / HF;
    const int n_edges = in_sizes[1];

    const int smem1 = (64 * HS2 + 8192) * 4;               // 50,176 B
    const int smem2 = (1256 + 1536 + 8 * 32 * 36) * 4;     // 48,032 B

    cudaFuncSetAttribute(precompute_kernel,
                         cudaFuncAttributeMaxDynamicSharedMemorySize, smem1);
    cudaFuncSetAttribute(edge_mlp_kernel,
                         cudaFuncAttributeMaxDynamicSharedMemorySize, smem2);

    init_frag_kernel<<<32, 256>>>(W1, W2);
    precompute_kernel<<<(n_nodes + 63) / 64, 256, smem1>>>(h, b1, n_nodes);
    edge_mlp_kernel<<<(n_edges + 255) / 256, 256, smem2>>>(
        src, dst, b2, W3, b3, out, n_edges);
}

// round 9
// speedup vs baseline: 9.0352x; 1.4132x over previous
#include <cuda_runtime.h>
#include <cuda_bf16.h>
#include <cuda_fp16.h>
#include <cstdint>

#define HF 128
#define MAX_NODES 100000

// Per-node precomputed layer-1 partials, fp16, b1 folded into A part:
// C[n][0:64] = h[n] @ W1[:, :128].T + b1 ; C[n][64:128] = h[n] @ W1[:, 128:].T
__device__ uint32_t g_C[(size_t)MAX_NODES * 64];
// One-shot fragment tables (fp16 half2, m16n8k16 B-frag order)
__device__ uint32_t g_Bh[8192];    // layer-1 weights G (128x128 rearranged W1)
__device__ uint32_t g_W2h[1024];   // layer-2 weights
__device__ uint32_t g_W3h[128];    // layer-3 weights (6 rows padded to 8)

__device__ __forceinline__ void mma_f16(float& c0, float& c1, float& c2, float& c3,
                                        uint32_t a0, uint32_t a1, uint32_t a2, uint32_t a3,
                                        uint32_t b0, uint32_t b1) {
    asm volatile(
        "mma.sync.aligned.m16n8k16.row.col.f32.f16.f16.f32 "
        "{%0,%1,%2,%3}, {%4,%5,%6,%7}, {%8,%9}, {%0,%1,%2,%3};"
        : "+f"(c0), "+f"(c1), "+f"(c2), "+f"(c3)
        : "r"(a0), "r"(a1), "r"(a2), "r"(a3), "r"(b0), "r"(b1));
}

__device__ __forceinline__ void ldsm_x4(uint32_t& r0, uint32_t& r1,
                                        uint32_t& r2, uint32_t& r3, uint32_t addr) {
    asm volatile("ldmatrix.sync.aligned.m8n8.x4.shared.b16 {%0,%1,%2,%3}, [%4];"
                 : "=r"(r0), "=r"(r1), "=r"(r2), "=r"(r3) : "r"(addr));
}

__device__ __forceinline__ uint32_t hadd_relu(uint32_t a, uint32_t b) {
    __half2 s = __hadd2(*(__half2*)&a, *(__half2*)&b);
    s = __hmax2(s, __half2half2(__float2half(0.f)));
    return *(uint32_t*)&s;
}

__device__ __forceinline__ uint32_t pack_h2(float x, float y) {
    __half2 v = __floats2half2_rn(x, y);
    return *(uint32_t*)&v;
}

__device__ __forceinline__ uint32_t pack_relu(float x, float y) {
    return pack_h2(fmaxf(x, 0.f), fmaxf(y, 0.f));
}

// ---------------------------------------------------------------------------
// Kernel 0: build fragment tables once (fp16 m16n8k16 B-frag order).
// Index law: entry (nt, kt, r, l): j = nt*8+(l>>2), kk = kt*16 + 2*(l&3) + r*8
// ---------------------------------------------------------------------------
__global__ void init_frag_kernel(const float* __restrict__ W1,
                                 const float* __restrict__ W2,
                                 const float* __restrict__ W3)
{
    int idx = blockIdx.x * 256 + threadIdx.x;
    if (idx < 8192) {
        int l  = idx & 31;
        int r  = (idx >> 5) & 1;
        int kt = (idx >> 6) & 7;
        int nt = idx >> 9;
        int j  = nt * 8 + (l >> 2);
        int kk = kt * 16 + 2 * (l & 3) + r * 8;
        float v0, v1;
        if (j < 64) { v0 = W1[j * 256 + kk];              v1 = W1[j * 256 + kk + 1]; }
        else        { v0 = W1[(j - 64) * 256 + 128 + kk]; v1 = W1[(j - 64) * 256 + 128 + kk + 1]; }
        g_Bh[idx] = pack_h2(v0, v1);
    }
    if (idx < 1024) {
        int l  = idx & 31;
        int r  = (idx >> 5) & 1;
        int kt = (idx >> 6) & 3;
        int nt = idx >> 8;
        int j  = nt * 8 + (l >> 2);
        int kk = kt * 16 + 2 * (l & 3) + r * 8;
        g_W2h[idx] = pack_h2(W2[j * 64 + kk], W2[j * 64 + kk + 1]);
    }
    if (idx < 128) {
        int l  = idx & 31;
        int r  = (idx >> 5) & 1;
        int kt = idx >> 6;
        int j  = l >> 2;                       // output class (pad 6,7 -> 0)
        int kk = kt * 16 + 2 * (l & 3) + r * 8;
        float v0 = (j < 6) ? W3[j * 32 + kk]     : 0.f;
        float v1 = (j < 6) ? W3[j * 32 + kk + 1] : 0.f;
        g_W3h[idx] = pack_h2(v0, v1);
    }
}

// ---------------------------------------------------------------------------
// Kernel 1: C = h @ G.T via fp16 mma m16n8k16, b1 as accumulator init,
// fp16 store. Block: 256 threads, 64 nodes. Warp w owns n-tiles {2w, 2w+1}.
// ---------------------------------------------------------------------------
#define HS2 68

__global__ __launch_bounds__(256, 3) void precompute_kernel(
    const float* __restrict__ h, const float* __restrict__ b1, int n_nodes)
{
    extern __shared__ uint32_t smu[];
    uint32_t* hs = smu;              // [64][HS2] = 4352 uints
    uint32_t* Bh = smu + 64 * HS2;   // 8192 uints

    const int tid  = threadIdx.x;
    const int lane = tid & 31;
    const int w    = tid >> 5;
    const int nb   = blockIdx.x * 64;

    // Copy Bh table (coalesced uint4)
    {
        uint4* dstp = (uint4*)Bh;
        const uint4* srcp = (const uint4*)g_Bh;
        #pragma unroll
        for (int i = 0; i < 8; ++i)
            dstp[i * 256 + tid] = srcp[i * 256 + tid];
    }
    // Stage 64 h rows as fp16
    #pragma unroll
    for (int i = 0; i < 8; ++i) {
        int idx = i * 256 + tid;
        int row = idx >> 5;
        int q   = idx & 31;
        int n   = nb + row;
        float4 v = make_float4(0.f, 0.f, 0.f, 0.f);
        if (n < n_nodes) v = ((const float4*)h)[(size_t)n * 32 + q];
        uint2 p = make_uint2(pack_h2(v.x, v.y), pack_h2(v.z, v.w));
        *(uint2*)(hs + row * HS2 + 2 * q) = p;
    }
    __syncthreads();

    const int g  = lane >> 2;
    const int cA = lane & 3;

    // b1 as accumulator init (A-part warps: w<4 -> cols 0..63)
    float bv0[2] = {0.f, 0.f}, bv1[2] = {0.f, 0.f};
    if (w < 4) {
        #pragma unroll
        for (int n = 0; n < 2; ++n) {
            int col = (2 * w + n) * 8 + 2 * cA;
            bv0[n] = b1[col];
            bv1[n] = b1[col + 1];
        }
    }

    float acc[4][2][4];
    #pragma unroll
    for (int m = 0; m < 4; ++m)
        #pragma unroll
        for (int n = 0; n < 2; ++n) {
            acc[m][n][0] = bv0[n]; acc[m][n][1] = bv1[n];
            acc[m][n][2] = bv0[n]; acc[m][n][3] = bv1[n];
        }

    #pragma unroll
    for (int kt = 0; kt < 8; ++kt) {
        uint32_t a[4][4];
        #pragma unroll
        for (int m = 0; m < 4; ++m) {
            int rA = m * 16 + g;
            a[m][0] = hs[rA * HS2 + kt * 8 + cA];
            a[m][1] = hs[(rA + 8) * HS2 + kt * 8 + cA];
            a[m][2] = hs[rA * HS2 + kt * 8 + cA + 4];
            a[m][3] = hs[(rA + 8) * HS2 + kt * 8 + cA + 4];
        }
        #pragma unroll
        for (int n = 0; n < 2; ++n) {
            int nt = 2 * w + n;
            uint32_t b0  = Bh[((nt * 8 + kt) * 2 + 0) * 32 + lane];
            uint32_t b1f = Bh[((nt * 8 + kt) * 2 + 1) * 32 + lane];
            #pragma unroll
            for (int m = 0; m < 4; ++m)
                mma_f16(acc[m][n][0], acc[m][n][1], acc[m][n][2], acc[m][n][3],
                        a[m][0], a[m][1], a[m][2], a[m][3], b0, b1f);
        }
    }

    // Store fp16. Cols (2cA, 2cA+1) pack to one half2 uint.
    #pragma unroll
    for (int m = 0; m < 4; ++m) {
        int r0 = nb + m * 16 + g;
        #pragma unroll
        for (int n = 0; n < 2; ++n) {
            int hcol = (2 * w + n) * 4 + cA;
            if (r0 < n_nodes)
                g_C[(size_t)r0 * 64 + hcol] = pack_h2(acc[m][n][0], acc[m][n][1]);
            if (r0 + 8 < n_nodes)
                g_C[(size_t)(r0 + 8) * 64 + hcol] = pack_h2(acc[m][n][2], acc[m][n][3]);
        }
    }
}

// ---------------------------------------------------------------------------
// Kernel 2: per-edge MLP, warp-autonomous 32-edge tiles, all-mma path.
//   Gather fp16 (b1 pre-folded) -> relu -> X in SMEM
//   Layer 2: fp16 mma (A via ldmatrix, b2 as accumulator init)
//   Layer 3: fp16 mma directly on layer-2 accumulator fragments (b3 as init);
//            no shfl, no staging — D-frag of L2 == A-frag of L3.
// ---------------------------------------------------------------------------
__global__ __launch_bounds__(256, 4) void edge_mlp_kernel(
    const int* __restrict__ src, const int* __restrict__ dst,
    const float* __restrict__ b2, const float* __restrict__ b3,
    float* __restrict__ out, int n_edges)
{
    extern __shared__ uint32_t smu[];
    uint32_t* W2h = smu;            // 1024
    uint32_t* Xs  = smu + 1024;     // 8 warps * 32 * 36 uints

    const int tid  = threadIdx.x;
    const int lane = tid & 31;
    const int w    = tid >> 5;

    // Issue edge-index loads early
    const int e0 = blockIdx.x * 256 + w * 32;
    const int eg = e0 + lane;
    const int s  = (eg < n_edges) ? src[eg] : 0;
    const int d  = (eg < n_edges) ? dst[eg] : 0;

    // Stage W2 frag table (256 uint4)
    ((uint4*)W2h)[tid] = ((const uint4*)g_W2h)[tid];
    __syncthreads();

    uint32_t* Xw = Xs + w * (32 * 36);
    const int q  = lane & 7;
    const int eh = lane >> 3;
    const uint4* Cu = (const uint4*)g_C;

    // Fused gather: X[el] = relu_h2(CA[src] + CB[dst])
    #pragma unroll
    for (int it = 0; it < 8; ++it) {
        int el   = it * 4 + eh;
        int srow = __shfl_sync(0xffffffffu, s, el);
        int drow = __shfl_sync(0xffffffffu, d, el);
        uint4 a = Cu[(size_t)srow * 16 + q];
        uint4 b = Cu[(size_t)drow * 16 + 8 + q];
        uint4 x;
        x.x = hadd_relu(a.x, b.x);
        x.y = hadd_relu(a.y, b.y);
        x.z = hadd_relu(a.z, b.z);
        x.w = hadd_relu(a.w, b.w);
        *(uint4*)(Xw + el * 36 + q * 4) = x;
    }
    __syncwarp();

    const int g  = lane >> 2;
    const int cA = lane & 3;

    // Layer 2: D[32x32] = X[32x64] @ W2T[64x32]; b2 as accumulator init
    float acc[2][4][4];
    #pragma unroll
    for (int n = 0; n < 4; ++n) {
        int col = n * 8 + 2 * cA;
        float v0 = __ldg(b2 + col), v1 = __ldg(b2 + col + 1);
        #pragma unroll
        for (int m = 0; m < 2; ++m) {
            acc[m][n][0] = v0; acc[m][n][1] = v1;
            acc[m][n][2] = v0; acc[m][n][3] = v1;
        }
    }

    uint32_t xw_addr = (uint32_t)__cvta_generic_to_shared(Xw);
    const int lrow  = (lane & 7) + ((lane >> 3) & 1) * 8;
    const int lcolh = (lane >> 4) * 8;
    uint32_t abase0 = xw_addr + (lrow * 36 + (lcolh >> 1)) * 4;   // m=0
    uint32_t abase1 = abase0 + 16 * 36 * 4;                       // m=1

    #pragma unroll
    for (int kt = 0; kt < 4; ++kt) {
        uint32_t A0[4], A1[4];
        ldsm_x4(A0[0], A0[1], A0[2], A0[3], abase0 + kt * 32);
        ldsm_x4(A1[0], A1[1], A1[2], A1[3], abase1 + kt * 32);
        #pragma unroll
        for (int n = 0; n < 4; ++n) {
            uint32_t b0  = W2h[((n * 4 + kt) * 2 + 0) * 32 + lane];
            uint32_t b1f = W2h[((n * 4 + kt) * 2 + 1) * 32 + lane];
            mma_f16(acc[0][n][0], acc[0][n][1], acc[0][n][2], acc[0][n][3],
                    A0[0], A0[1], A0[2], A0[3], b0, b1f);
            mma_f16(acc[1][n][0], acc[1][n][1], acc[1][n][2], acc[1][n][3],
                    A1[0], A1[1], A1[2], A1[3], b0, b1f);
        }
    }

    // Layer 3 as mma: Z[32x8] = relu(Y)[32x32] @ W3T[32x8]; b3 as init.
    // A-frags come directly from layer-2 accumulators (relu + pack).
    float zb0 = (cA < 3) ? __ldg(b3 + 2 * cA)     : 0.f;
    float zb1 = (cA < 3) ? __ldg(b3 + 2 * cA + 1) : 0.f;
    float zc[2][4];
    #pragma unroll
    for (int m = 0; m < 2; ++m) {
        zc[m][0] = zb0; zc[m][1] = zb1; zc[m][2] = zb0; zc[m][3] = zb1;
    }

    uint32_t w3f[2][2];
    #pragma unroll
    for (int kt = 0; kt < 2; ++kt) {
        w3f[kt][0] = g_W3h[(kt * 2 + 0) * 32 + lane];
        w3f[kt][1] = g_W3h[(kt * 2 + 1) * 32 + lane];
    }

    #pragma unroll
    for (int m = 0; m < 2; ++m)
        #pragma unroll
        for (int kt = 0; kt < 2; ++kt) {
            uint32_t a0 = pack_relu(acc[m][2 * kt][0],     acc[m][2 * kt][1]);
            uint32_t a1 = pack_relu(acc[m][2 * kt][2],     acc[m][2 * kt][3]);
            uint32_t a2 = pack_relu(acc[m][2 * kt + 1][0], acc[m][2 * kt + 1][1]);
            uint32_t a3 = pack_relu(acc[m][2 * kt + 1][2], acc[m][2 * kt + 1][3]);
            mma_f16(zc[m][0], zc[m][1], zc[m][2], zc[m][3],
                    a0, a1, a2, a3, w3f[kt][0], w3f[kt][1]);
        }

    // Store: thread owns rows (m*16+g, +8), cols (2cA, 2cA+1); cA==3 -> pad cols
    if (cA < 3) {
        #pragma unroll
        for (int m = 0; m < 2; ++m) {
            int e1 = e0 + m * 16 + g;
            if (e1 < n_edges)
                *(float2*)&out[(size_t)e1 * 6 + 2 * cA] = make_float2(zc[m][0], zc[m][1]);
            int e2 = e1 + 8;
            if (e2 < n_edges)
                *(float2*)&out[(size_t)e2 * 6 + 2 * cA] = make_float2(zc[m][2], zc[m][3]);
        }
    }
}

// ---------------------------------------------------------------------------
// Launch
// ---------------------------------------------------------------------------
extern "C" void kernel_launch(void* const* d_in, const int* in_sizes, int n_in,
                              void* d_out, int out_size)
{
    const float* h   = (const float*)d_in[0];
    const int*   src = (const int*)  d_in[1];
    const int*   dst = (const int*)  d_in[2];
    const float* W1  = (const float*)d_in[3];
    const float* b1  = (const float*)d_in[4];
    const float* W2  = (const float*)d_in[5];
    const float* b2  = (const float*)d_in[6];
    const float* W3  = (const float*)d_in[7];
    const float* b3  = (const float*)d_in[8];
    float* out = (float*)d_out;

    const int n_nodes = in_sizes[0] / HF;
    const int n_edges = in_sizes[1];

    const int smem1 = (64 * HS2 + 8192) * 4;         // 50,176 B
    const int smem2 = (1024 + 8 * 32 * 36) * 4;      // 40,960 B

    cudaFuncSetAttribute(precompute_kernel,
                         cudaFuncAttributeMaxDynamicSharedMemorySize, smem1);
    cudaFuncSetAttribute(edge_mlp_kernel,
                         cudaFuncAttributeMaxDynamicSharedMemorySize, smem2);

    init_frag_kernel<<<32, 256>>>(W1, W2, W3);
    precompute_kernel<<<(n_nodes + 63) / 64, 256, smem1>>>(h, b1, n_nodes);
    edge_mlp_kernel<<<(n_edges + 255) / 256, 256, smem2>>>(
        src, dst, b2, b3, out, n_edges);
}

// round 10
// speedup vs baseline: 9.0428x; 1.0008x over previous
#include <cuda_runtime.h>
#include <cuda_bf16.h>
#include <cuda_fp16.h>
#include <cstdint>

#define HF 128
#define MAX_NODES 100000

// Per-node precomputed layer-1 partials, fp16, b1 folded into A part:
// C[n][0:64] = h[n] @ W1[:, :128].T + b1 ; C[n][64:128] = h[n] @ W1[:, 128:].T
__device__ uint32_t g_C[(size_t)MAX_NODES * 64];
// One-shot fragment tables (fp16 half2, m16n8k16 B-frag order)
__device__ uint32_t g_Bh[8192];    // layer-1 weights G (128x128 rearranged W1)
__device__ uint32_t g_W2h[1024];   // layer-2 weights
__device__ uint32_t g_W3h[128];    // layer-3 weights (6 rows padded to 8)

__device__ __forceinline__ void mma_f16(float& c0, float& c1, float& c2, float& c3,
                                        uint32_t a0, uint32_t a1, uint32_t a2, uint32_t a3,
                                        uint32_t b0, uint32_t b1) {
    asm volatile(
        "mma.sync.aligned.m16n8k16.row.col.f32.f16.f16.f32 "
        "{%0,%1,%2,%3}, {%4,%5,%6,%7}, {%8,%9}, {%0,%1,%2,%3};"
        : "+f"(c0), "+f"(c1), "+f"(c2), "+f"(c3)
        : "r"(a0), "r"(a1), "r"(a2), "r"(a3), "r"(b0), "r"(b1));
}

__device__ __forceinline__ void ldsm_x4(uint32_t& r0, uint32_t& r1,
                                        uint32_t& r2, uint32_t& r3, uint32_t addr) {
    asm volatile("ldmatrix.sync.aligned.m8n8.x4.shared.b16 {%0,%1,%2,%3}, [%4];"
                 : "=r"(r0), "=r"(r1), "=r"(r2), "=r"(r3) : "r"(addr));
}

__device__ __forceinline__ uint32_t hadd_relu(uint32_t a, uint32_t b) {
    __half2 s = __hadd2(*(__half2*)&a, *(__half2*)&b);
    s = __hmax2(s, __half2half2(__float2half(0.f)));
    return *(uint32_t*)&s;
}

__device__ __forceinline__ uint32_t pack_h2(float x, float y) {
    __half2 v = __floats2half2_rn(x, y);
    return *(uint32_t*)&v;
}

__device__ __forceinline__ uint32_t pack_relu(float x, float y) {
    return pack_h2(fmaxf(x, 0.f), fmaxf(y, 0.f));
}

// ---------------------------------------------------------------------------
// Kernel 0: build fragment tables once (fp16 m16n8k16 B-frag order).
// Index law: entry (nt, kt, r, l): j = nt*8+(l>>2), kk = kt*16 + 2*(l&3) + r*8
// ---------------------------------------------------------------------------
__global__ void init_frag_kernel(const float* __restrict__ W1,
                                 const float* __restrict__ W2,
                                 const float* __restrict__ W3)
{
    int idx = blockIdx.x * 256 + threadIdx.x;
    if (idx < 8192) {
        int l  = idx & 31;
        int r  = (idx >> 5) & 1;
        int kt = (idx >> 6) & 7;
        int nt = idx >> 9;
        int j  = nt * 8 + (l >> 2);
        int kk = kt * 16 + 2 * (l & 3) + r * 8;
        float v0, v1;
        if (j < 64) { v0 = W1[j * 256 + kk];              v1 = W1[j * 256 + kk + 1]; }
        else        { v0 = W1[(j - 64) * 256 + 128 + kk]; v1 = W1[(j - 64) * 256 + 128 + kk + 1]; }
        g_Bh[idx] = pack_h2(v0, v1);
    }
    if (idx < 1024) {
        int l  = idx & 31;
        int r  = (idx >> 5) & 1;
        int kt = (idx >> 6) & 3;
        int nt = idx >> 8;
        int j  = nt * 8 + (l >> 2);
        int kk = kt * 16 + 2 * (l & 3) + r * 8;
        g_W2h[idx] = pack_h2(W2[j * 64 + kk], W2[j * 64 + kk + 1]);
    }
    if (idx < 128) {
        int l  = idx & 31;
        int r  = (idx >> 5) & 1;
        int kt = idx >> 6;
        int j  = l >> 2;                       // output class (pad 6,7 -> 0)
        int kk = kt * 16 + 2 * (l & 3) + r * 8;
        float v0 = (j < 6) ? W3[j * 32 + kk]     : 0.f;
        float v1 = (j < 6) ? W3[j * 32 + kk + 1] : 0.f;
        g_W3h[idx] = pack_h2(v0, v1);
    }
}

// ---------------------------------------------------------------------------
// Kernel 1: C = h @ G.T via fp16 mma, persistent blocks (Bh copied ONCE per
// block, then loop over node tiles). 256 thr, 64 nodes/tile.
// ---------------------------------------------------------------------------
#define HS2 68
#define PRE_GRID 444   // 148 SMs * 3 blocks

__global__ __launch_bounds__(256, 3) void precompute_kernel(
    const float* __restrict__ h, const float* __restrict__ b1,
    int n_nodes, int n_tiles)
{
    extern __shared__ uint32_t smu[];
    uint32_t* hs = smu;              // [64][HS2] = 4352 uints
    uint32_t* Bh = smu + 64 * HS2;   // 8192 uints

    const int tid  = threadIdx.x;
    const int lane = tid & 31;
    const int w    = tid >> 5;

    // Copy Bh table once per block (coalesced uint4)
    {
        uint4* dstp = (uint4*)Bh;
        const uint4* srcp = (const uint4*)g_Bh;
        #pragma unroll
        for (int i = 0; i < 8; ++i)
            dstp[i * 256 + tid] = srcp[i * 256 + tid];
    }

    const int g  = lane >> 2;
    const int cA = lane & 3;

    // b1 fold (loop-invariant; A-part warps: w<4 -> cols 0..63)
    float bv0[2] = {0.f, 0.f}, bv1[2] = {0.f, 0.f};
    if (w < 4) {
        #pragma unroll
        for (int n = 0; n < 2; ++n) {
            int col = (2 * w + n) * 8 + 2 * cA;
            bv0[n] = b1[col];
            bv1[n] = b1[col + 1];
        }
    }

    for (int t = blockIdx.x; t < n_tiles; t += PRE_GRID) {
        const int nb = t * 64;
        __syncthreads();   // hs reusable (also orders Bh copy on 1st iter)

        // Stage 64 h rows as fp16
        #pragma unroll
        for (int i = 0; i < 8; ++i) {
            int idx = i * 256 + tid;
            int row = idx >> 5;
            int q   = idx & 31;
            int n   = nb + row;
            float4 v = make_float4(0.f, 0.f, 0.f, 0.f);
            if (n < n_nodes) v = ((const float4*)h)[(size_t)n * 32 + q];
            uint2 p = make_uint2(pack_h2(v.x, v.y), pack_h2(v.z, v.w));
            *(uint2*)(hs + row * HS2 + 2 * q) = p;
        }
        __syncthreads();

        float acc[4][2][4];
        #pragma unroll
        for (int m = 0; m < 4; ++m)
            #pragma unroll
            for (int n = 0; n < 2; ++n) {
                acc[m][n][0] = bv0[n]; acc[m][n][1] = bv1[n];
                acc[m][n][2] = bv0[n]; acc[m][n][3] = bv1[n];
            }

        #pragma unroll
        for (int kt = 0; kt < 8; ++kt) {
            uint32_t a[4][4];
            #pragma unroll
            for (int m = 0; m < 4; ++m) {
                int rA = m * 16 + g;
                a[m][0] = hs[rA * HS2 + kt * 8 + cA];
                a[m][1] = hs[(rA + 8) * HS2 + kt * 8 + cA];
                a[m][2] = hs[rA * HS2 + kt * 8 + cA + 4];
                a[m][3] = hs[(rA + 8) * HS2 + kt * 8 + cA + 4];
            }
            #pragma unroll
            for (int n = 0; n < 2; ++n) {
                int nt = 2 * w + n;
                uint32_t b0  = Bh[((nt * 8 + kt) * 2 + 0) * 32 + lane];
                uint32_t b1f = Bh[((nt * 8 + kt) * 2 + 1) * 32 + lane];
                #pragma unroll
                for (int m = 0; m < 4; ++m)
                    mma_f16(acc[m][n][0], acc[m][n][1], acc[m][n][2], acc[m][n][3],
                            a[m][0], a[m][1], a[m][2], a[m][3], b0, b1f);
            }
        }

        // Store fp16. Cols (2cA, 2cA+1) pack to one half2 uint.
        #pragma unroll
        for (int m = 0; m < 4; ++m) {
            int r0 = nb + m * 16 + g;
            #pragma unroll
            for (int n = 0; n < 2; ++n) {
                int hcol = (2 * w + n) * 4 + cA;
                if (r0 < n_nodes)
                    g_C[(size_t)r0 * 64 + hcol] = pack_h2(acc[m][n][0], acc[m][n][1]);
                if (r0 + 8 < n_nodes)
                    g_C[(size_t)(r0 + 8) * 64 + hcol] = pack_h2(acc[m][n][2], acc[m][n][3]);
            }
        }
    }
}

// ---------------------------------------------------------------------------
// Kernel 2: per-edge MLP, warp-autonomous 32-edge tiles, all-mma path.
// No block barrier: W2/W3 fragments read directly from L1-resident global
// tables; warps independent from cycle 0.
// ---------------------------------------------------------------------------
__global__ __launch_bounds__(256, 4) void edge_mlp_kernel(
    const int* __restrict__ src, const int* __restrict__ dst,
    const float* __restrict__ b2, const float* __restrict__ b3,
    float* __restrict__ out, int n_edges)
{
    extern __shared__ uint32_t smu[];
    uint32_t* Xs = smu;             // 8 warps * 32 * 36 uints

    const int tid  = threadIdx.x;
    const int lane = tid & 31;
    const int w    = tid >> 5;

    const int e0 = blockIdx.x * 256 + w * 32;
    const int eg = e0 + lane;
    const int s  = (eg < n_edges) ? src[eg] : 0;
    const int d  = (eg < n_edges) ? dst[eg] : 0;

    uint32_t* Xw = Xs + w * (32 * 36);
    const int q  = lane & 7;
    const int eh = lane >> 3;
    const uint4* Cu = (const uint4*)g_C;

    // Fused gather: X[el] = relu_h2(CA[src] + CB[dst])
    #pragma unroll
    for (int it = 0; it < 8; ++it) {
        int el   = it * 4 + eh;
        int srow = __shfl_sync(0xffffffffu, s, el);
        int drow = __shfl_sync(0xffffffffu, d, el);
        uint4 a = Cu[(size_t)srow * 16 + q];
        uint4 b = Cu[(size_t)drow * 16 + 8 + q];
        uint4 x;
        x.x = hadd_relu(a.x, b.x);
        x.y = hadd_relu(a.y, b.y);
        x.z = hadd_relu(a.z, b.z);
        x.w = hadd_relu(a.w, b.w);
        *(uint4*)(Xw + el * 36 + q * 4) = x;
    }
    __syncwarp();

    const int g  = lane >> 2;
    const int cA = lane & 3;

    // Layer 2: D[32x32] = X[32x64] @ W2T[64x32]; b2 as accumulator init
    float acc[2][4][4];
    #pragma unroll
    for (int n = 0; n < 4; ++n) {
        int col = n * 8 + 2 * cA;
        float v0 = __ldg(b2 + col), v1 = __ldg(b2 + col + 1);
        #pragma unroll
        for (int m = 0; m < 2; ++m) {
            acc[m][n][0] = v0; acc[m][n][1] = v1;
            acc[m][n][2] = v0; acc[m][n][3] = v1;
        }
    }

    uint32_t xw_addr = (uint32_t)__cvta_generic_to_shared(Xw);
    const int lrow  = (lane & 7) + ((lane >> 3) & 1) * 8;
    const int lcolh = (lane >> 4) * 8;
    uint32_t abase0 = xw_addr + (lrow * 36 + (lcolh >> 1)) * 4;   // m=0
    uint32_t abase1 = abase0 + 16 * 36 * 4;                       // m=1

    #pragma unroll
    for (int kt = 0; kt < 4; ++kt) {
        uint32_t A0[4], A1[4];
        ldsm_x4(A0[0], A0[1], A0[2], A0[3], abase0 + kt * 32);
        ldsm_x4(A1[0], A1[1], A1[2], A1[3], abase1 + kt * 32);
        #pragma unroll
        for (int n = 0; n < 4; ++n) {
            uint32_t b0  = __ldg(&g_W2h[((n * 4 + kt) * 2 + 0) * 32 + lane]);
            uint32_t b1f = __ldg(&g_W2h[((n * 4 + kt) * 2 + 1) * 32 + lane]);
            mma_f16(acc[0][n][0], acc[0][n][1], acc[0][n][2], acc[0][n][3],
                    A0[0], A0[1], A0[2], A0[3], b0, b1f);
            mma_f16(acc[1][n][0], acc[1][n][1], acc[1][n][2], acc[1][n][3],
                    A1[0], A1[1], A1[2], A1[3], b0, b1f);
        }
    }

    // Layer 3 as mma: Z[32x8] = relu(Y)[32x32] @ W3T[32x8]; b3 as init.
    float zb0 = (cA < 3) ? __ldg(b3 + 2 * cA)     : 0.f;
    float zb1 = (cA < 3) ? __ldg(b3 + 2 * cA + 1) : 0.f;
    float zc[2][4];
    #pragma unroll
    for (int m = 0; m < 2; ++m) {
        zc[m][0] = zb0; zc[m][1] = zb1; zc[m][2] = zb0; zc[m][3] = zb1;
    }

    uint32_t w3f[2][2];
    #pragma unroll
    for (int kt = 0; kt < 2; ++kt) {
        w3f[kt][0] = __ldg(&g_W3h[(kt * 2 + 0) * 32 + lane]);
        w3f[kt][1] = __ldg(&g_W3h[(kt * 2 + 1) * 32 + lane]);
    }

    #pragma unroll
    for (int m = 0; m < 2; ++m)
        #pragma unroll
        for (int kt = 0; kt < 2; ++kt) {
            uint32_t a0 = pack_relu(acc[m][2 * kt][0],     acc[m][2 * kt][1]);
            uint32_t a1 = pack_relu(acc[m][2 * kt][2],     acc[m][2 * kt][3]);
            uint32_t a2 = pack_relu(acc[m][2 * kt + 1][0], acc[m][2 * kt + 1][1]);
            uint32_t a3 = pack_relu(acc[m][2 * kt + 1][2], acc[m][2 * kt + 1][3]);
            mma_f16(zc[m][0], zc[m][1], zc[m][2], zc[m][3],
                    a0, a1, a2, a3, w3f[kt][0], w3f[kt][1]);
        }

    // Store: thread owns rows (m*16+g, +8), cols (2cA, 2cA+1); cA==3 -> pad
    if (cA < 3) {
        #pragma unroll
        for (int m = 0; m < 2; ++m) {
            int e1 = e0 + m * 16 + g;
            if (e1 < n_edges)
                *(float2*)&out[(size_t)e1 * 6 + 2 * cA] = make_float2(zc[m][0], zc[m][1]);
            int e2 = e1 + 8;
            if (e2 < n_edges)
                *(float2*)&out[(size_t)e2 * 6 + 2 * cA] = make_float2(zc[m][2], zc[m][3]);
        }
    }
}

// ---------------------------------------------------------------------------
// Launch
// ---------------------------------------------------------------------------
extern "C" void kernel_launch(void* const* d_in, const int* in_sizes, int n_in,
                              void* d_out, int out_size)
{
    const float* h   = (const float*)d_in[0];
    const int*   src = (const int*)  d_in[1];
    const int*   dst = (const int*)  d_in[2];
    const float* W1  = (const float*)d_in[3];
    const float* b1  = (const float*)d_in[4];
    const float* W2  = (const float*)d_in[5];
    const float* b2  = (const float*)d_in[6];
    const float* W3  = (const float*)d_in[7];
    const float* b3  = (const float*)d_in[8];
    float* out = (float*)d_out;

    const int n_nodes = in_sizes[0] / HF;
    const int n_edges = in_sizes[1];
    const int n_tiles = (n_nodes + 63) / 64;

    const int smem1 = (64 * HS2 + 8192) * 4;      // 50,176 B
    const int smem2 = (8 * 32 * 36) * 4;          // 36,864 B

    cudaFuncSetAttribute(precompute_kernel,
                         cudaFuncAttributeMaxDynamicSharedMemorySize, smem1);
    cudaFuncSetAttribute(edge_mlp_kernel,
                         cudaFuncAttributeMaxDynamicSharedMemorySize, smem2);

    init_frag_kernel<<<32, 256>>>(W1, W2, W3);
    precompute_kernel<<<PRE_GRID, 256, smem1>>>(h, b1, n_nodes, n_tiles);
    edge_mlp_kernel<<<(n_edges + 255) / 256, 256, smem2>>>(
        src, dst, b2, b3, out, n_edges);
}